// round 1
// baseline (speedup 1.0000x reference)
#include <cuda_runtime.h>

// ---------------------------------------------------------------------------
// GeometricTerm: indices = rois[:,0] (int64); geo[n,k,h,w] (fp32)
//
// Algebraic restructuring:
//   img[h,w,o] = imgx[h,o] + imgy[w,o]      (pos = concat(emb(h), emb(w)))
//   geo[nk,h,w] = Gx[nk,h] + Gy[nk,w]
// so the 9.9 GMAC final einsum collapses into two skinny GEMMs + broadcast add.
// ---------------------------------------------------------------------------

#define N_ROIS 128
#define CEMB   512
#define HH     64
#define WW     96
#define KO     12544   /* 49*256 */
#define NK     6272    /* 128*49 */
#define GEO_SIZE 38535168ll  /* 128*49*64*96 */

// scratch (static device globals; no allocation allowed)
__device__ float g_eps [N_ROIS * 2048];
__device__ float g_ex  [HH * CEMB];
__device__ float g_ey  [WW * CEMB];
__device__ float g_v   [N_ROIS * CEMB];
__device__ float g_box [N_ROIS * KO];     // row-major [128,12544] == [6272,256]
__device__ float g_imgx[HH * 256];
__device__ float g_imgy[WW * 256];
__device__ float g_gx  [NK * HH];
__device__ float g_gy  [NK * WW];

// ---------------------------------------------------------------------------
// sinusoid embedding, computed in fp64 to match JAX fp32 reference closely:
// i<256: sin(z / 1000^((2i+1)/512)); i>=256: cos(z / 1000^((2(i-256))/512))
// ---------------------------------------------------------------------------
__device__ __forceinline__ float emb_val(float z, int i) {
    const double LOG1000_OVER_C = 6.907755278982137 / 512.0;
    double e = (i < 256) ? (double)(2 * i + 1) : (double)(2 * (i - 256));
    double den = exp(e * LOG1000_OVER_C);
    double a = (double)z / den;
    return (i < 256) ? (float)sin(a) : (float)cos(a);
}

__global__ void emb_rois_kernel(const float* __restrict__ rois) {
    int idx = blockIdx.x * blockDim.x + threadIdx.x;
    if (idx >= N_ROIS * 2048) return;
    int n = idx >> 11;
    int d = idx & 2047;
    int j = d >> 9;        // which of 4 coordinates
    int i = d & 511;       // position within 512-dim embedding
    float z = rois[n * 5 + 1 + j];
    g_eps[idx] = emb_val(z, i);
}

__global__ void emb_range_kernel(int which) {
    int idx = blockIdx.x * blockDim.x + threadIdx.x;
    int rows = which ? WW : HH;
    if (idx >= rows * CEMB) return;
    float* out = which ? g_ey : g_ex;
    int r = idx >> 9;
    int i = idx & 511;
    out[idx] = emb_val((float)r, i);
}

// ---------------------------------------------------------------------------
// Tiled SGEMM:  C[m,n] = sum_k A[m*lda+k] * B[n*ldb+k]   (A @ B^T, K contig)
// 64x64 tile, BK=16, 256 threads, 4x4 per-thread microtile.
// Requires K % 16 == 0 (all call sites satisfy this).
// ---------------------------------------------------------------------------
__global__ void __launch_bounds__(256)
gemm_abT(const float* __restrict__ A, int lda,
         const float* __restrict__ B, int ldb,
         float* __restrict__ C, int ldc,
         int M, int N, int K)
{
    __shared__ float As[16][64];
    __shared__ float Bs[16][64];

    int tid = threadIdx.x;
    int tx = tid & 15;         // n-direction
    int ty = tid >> 4;         // m-direction
    int m0 = blockIdx.y * 64;
    int n0 = blockIdx.x * 64;

    // loader mapping: each thread loads one float4 of A-tile and one of B-tile
    int lr = tid >> 2;           // 0..63  (tile row)
    int lc = (tid & 3) * 4;      // 0,4,8,12 (k offset)
    const float* Aptr = A + (size_t)(m0 + lr) * lda + lc;
    const float* Bptr = B + (size_t)(n0 + lr) * ldb + lc;
    bool aval = (m0 + lr) < M;
    bool bval = (n0 + lr) < N;

    float acc[4][4];
#pragma unroll
    for (int i = 0; i < 4; i++)
#pragma unroll
        for (int j = 0; j < 4; j++) acc[i][j] = 0.f;

    for (int k0 = 0; k0 < K; k0 += 16) {
        float4 av = aval ? *(const float4*)(Aptr + k0) : make_float4(0.f, 0.f, 0.f, 0.f);
        float4 bv = bval ? *(const float4*)(Bptr + k0) : make_float4(0.f, 0.f, 0.f, 0.f);
        __syncthreads();   // previous iteration's reads done before overwrite
        As[lc + 0][lr] = av.x; As[lc + 1][lr] = av.y;
        As[lc + 2][lr] = av.z; As[lc + 3][lr] = av.w;
        Bs[lc + 0][lr] = bv.x; Bs[lc + 1][lr] = bv.y;
        Bs[lc + 2][lr] = bv.z; Bs[lc + 3][lr] = bv.w;
        __syncthreads();
#pragma unroll
        for (int kk = 0; kk < 16; kk++) {
            float4 a = *(const float4*)&As[kk][ty * 4];
            float4 b = *(const float4*)&Bs[kk][tx * 4];
            acc[0][0] += a.x * b.x; acc[0][1] += a.x * b.y;
            acc[0][2] += a.x * b.z; acc[0][3] += a.x * b.w;
            acc[1][0] += a.y * b.x; acc[1][1] += a.y * b.y;
            acc[1][2] += a.y * b.z; acc[1][3] += a.y * b.w;
            acc[2][0] += a.z * b.x; acc[2][1] += a.z * b.y;
            acc[2][2] += a.z * b.z; acc[2][3] += a.z * b.w;
            acc[3][0] += a.w * b.x; acc[3][1] += a.w * b.y;
            acc[3][2] += a.w * b.z; acc[3][3] += a.w * b.w;
        }
    }

#pragma unroll
    for (int i = 0; i < 4; i++) {
        int m = m0 + ty * 4 + i;
        if (m >= M) continue;
#pragma unroll
        for (int j = 0; j < 4; j++) {
            int n = n0 + tx * 4 + j;
            if (n < N) C[(size_t)m * ldc + n] = acc[i][j];
        }
    }
}

// ---------------------------------------------------------------------------
// Final assemble: geo[nk, h, w] = Gx[nk,h] + Gy[nk,w]   (pure broadcast add)
// One block per nk; float4 stores (6144 floats per block).
// ---------------------------------------------------------------------------
__global__ void __launch_bounds__(256)
assemble_kernel(float* __restrict__ outg)
{
    int nk = blockIdx.x;
    __shared__ float sx[HH];
    __shared__ float sy[WW];
    int tid = threadIdx.x;
    if (tid < HH) sx[tid] = g_gx[nk * HH + tid];
    if (tid >= HH && tid < HH + WW) sy[tid - HH] = g_gy[nk * WW + (tid - HH)];
    __syncthreads();

    float* base = outg + (size_t)nk * (HH * WW);
#pragma unroll
    for (int t = tid; t < (HH * WW) / 4; t += 256) {
        int h  = t / 24;           // 96/4 = 24 float4 per row
        int w4 = (t % 24) * 4;
        float gx = sx[h];
        float4 v = make_float4(gx + sy[w4 + 0], gx + sy[w4 + 1],
                               gx + sy[w4 + 2], gx + sy[w4 + 3]);
        *(float4*)(base + h * WW + w4) = v;
    }
}

__global__ void indices_kernel(const float* __restrict__ rois, void* d_out, int mode) {
    int i = threadIdx.x;
    if (i >= N_ROIS) return;
    long long v = (long long)rois[i * 5];
    if (mode == 1)       ((float*)d_out)[i] = (float)v;
    else if (mode == 2)  ((long long*)d_out)[i] = v;
}

// ---------------------------------------------------------------------------
extern "C" void kernel_launch(void* const* d_in, const int* in_sizes, int n_in,
                              void* d_out, int out_size)
{
    // inputs (metadata order): input, rois, V_box, W_box, W_im
    const float* rois  = (const float*)d_in[1];
    const float* V_box = (const float*)d_in[2];
    const float* W_box = (const float*)d_in[3];
    const float* W_im  = (const float*)d_in[4];

    float *eps, *ex, *ey, *v, *box, *imgx, *imgy, *gx, *gy;
    cudaGetSymbolAddress((void**)&eps,  g_eps);
    cudaGetSymbolAddress((void**)&ex,   g_ex);
    cudaGetSymbolAddress((void**)&ey,   g_ey);
    cudaGetSymbolAddress((void**)&v,    g_v);
    cudaGetSymbolAddress((void**)&box,  g_box);
    cudaGetSymbolAddress((void**)&imgx, g_imgx);
    cudaGetSymbolAddress((void**)&imgy, g_imgy);
    cudaGetSymbolAddress((void**)&gx,   g_gx);
    cudaGetSymbolAddress((void**)&gy,   g_gy);

    long long extra = (long long)out_size - GEO_SIZE;
    int mode = (extra == 128) ? 1 : (extra == 256 ? 2 : 0);
    float* outg = (float*)d_out + (extra > 0 ? extra : 0);

    // 1) embeddings (fp64 internal for fidelity vs JAX fp32 ref)
    emb_rois_kernel<<<(N_ROIS * 2048 + 255) / 256, 256>>>(rois);
    emb_range_kernel<<<(HH * CEMB + 255) / 256, 256>>>(0);
    emb_range_kernel<<<(WW * CEMB + 255) / 256, 256>>>(1);

    // 2) v = eps @ V_box^T                       [128,512],  K=2048
    gemm_abT<<<dim3(512 / 64, 128 / 64), 256>>>(eps, 2048, V_box, 2048,
                                                v, 512, 128, 512, 2048);

    // 3) imgx = ex @ W_im[:, :512]^T             [64,256],   K=512
    gemm_abT<<<dim3(256 / 64, 1), 256>>>(ex, CEMB, W_im, 1024,
                                         imgx, 256, HH, 256, 512);
    //    imgy = ey @ W_im[:, 512:]^T             [96,256],   K=512
    gemm_abT<<<dim3(256 / 64, 2), 256>>>(ey, CEMB, W_im + 512, 1024,
                                         imgy, 256, WW, 256, 512);

    // 4) box = v @ W_box^T                       [128,12544], K=512 (dominant)
    gemm_abT<<<dim3(KO / 64, 2), 256>>>(v, 512, W_box, 512,
                                        box, KO, 128, KO, 512);

    // 5) Gx = box @ imgx^T   [6272,64], K=256 ;  Gy = box @ imgy^T  [6272,96]
    gemm_abT<<<dim3(1, NK / 64), 256>>>(box, 256, imgx, 256,
                                        gx, HH, NK, HH, 256);
    gemm_abT<<<dim3(2, NK / 64), 256>>>(box, 256, imgy, 256,
                                        gy, WW, NK, WW, 256);

    // 6) indices + broadcast-add assembly of geo
    if (mode) indices_kernel<<<1, 128>>>(rois, d_out, mode);
    assemble_kernel<<<NK, 256>>>(outg);
}

// round 3
// speedup vs baseline: 1.8331x; 1.8331x over previous
#include <cuda_runtime.h>

// ---------------------------------------------------------------------------
// GeometricTerm: indices = rois[:,0]; geo[n,k,h,w] (fp32)
//   img[h,w,o] = imgx[h,o] + imgy[w,o]  =>  geo[nk,h,w] = Gx[nk,h] + Gy[nk,w]
// Pipeline: emb -> v (split-K) -> imgxy (split-K) -> box -> Gxy -> assemble
// ---------------------------------------------------------------------------

#define N_ROIS 128
#define CEMB   512
#define HH     64
#define WW     96
#define KO     12544   /* 49*256 */
#define NK     6272    /* 128*49 */
#define GEO_SIZE 38535168ll  /* 128*49*64*96 */

__device__ float g_eps  [N_ROIS * 2048];
__device__ float g_ex   [HH * CEMB];
__device__ float g_ey   [WW * CEMB];
__device__ float g_v    [N_ROIS * CEMB];
__device__ float g_box  [N_ROIS * KO];      // [128,12544] == [6272,256]
__device__ float g_imgxy[160 * 256];        // rows 0-63 imgx, 64-159 imgy
__device__ float g_gxy  [NK * 160];         // cols 0-63 Gx(h), 64-159 Gy(w)
__device__ float g_partA[8 * N_ROIS * CEMB];   // v split-K partials
__device__ float g_partB[2 * 160 * 256];       // imgxy split-K partials

// ---------------------------------------------------------------------------
// sinusoid embedding in fp64 (matches JAX fp32 ref to ~1e-6)
// ---------------------------------------------------------------------------
__device__ __forceinline__ float emb_val(float z, int i) {
    const double LOG1000_OVER_C = 6.907755278982137 / 512.0;
    double e = (i < 256) ? (double)(2 * i + 1) : (double)(2 * (i - 256));
    double den = exp(e * LOG1000_OVER_C);
    double a = (double)z / den;
    return (i < 256) ? (float)sin(a) : (float)cos(a);
}

__global__ void emb_rois_kernel(const float* __restrict__ rois) {
    int idx = blockIdx.x * blockDim.x + threadIdx.x;
    if (idx >= N_ROIS * 2048) return;
    int n = idx >> 11, d = idx & 2047;
    int j = d >> 9, i = d & 511;
    g_eps[idx] = emb_val(rois[n * 5 + 1 + j], i);
}

__global__ void emb_range_kernel(int which) {
    int idx = blockIdx.x * blockDim.x + threadIdx.x;
    int rows = which ? WW : HH;
    if (idx >= rows * CEMB) return;
    float* out = which ? g_ey : g_ex;
    out[idx] = emb_val((float)(idx >> 9), idx & 511);
}

// ---------------------------------------------------------------------------
// Templated SGEMM  C[m,n] = sum_k A[m,k]*B[n,k]   (A @ B^T, K contiguous)
// 256 threads; TM x TN microtile; double-buffered smem; register prefetch;
// one __syncthreads per K-tile. Optional split-K via blockIdx.z:
// each z-chunk writes its full tile at C + z*partStride (deterministic).
// Requires: (BM/TM)*(BN/TN)==256, BM*BK>=1024, BN*BK>=1024, K%BK==0,
//           kchunk%BK==0, TM%2==0, TN%4==0.
// ---------------------------------------------------------------------------
template<int BM, int BN, int BK, int TM, int TN>
__global__ void __launch_bounds__(256)
gemm_tpl(const float* __restrict__ A, int lda,
         const float* __restrict__ B, int ldb,
         float* __restrict__ C, int ldc, long long partStride,
         int M, int N, int K, int kchunk)
{
    constexpr int TX = BN / TN;          // threads along n
    constexpr int TY = BM / TM;          // threads along m
    static_assert(TX * TY == 256, "thread shape");
    constexpr int LA = BM * BK / 1024;   // float4 loads per thread for A
    constexpr int LB = BN * BK / 1024;
    constexpr int KQ = BK / 4;

    __shared__ float As[2][BK][BM];
    __shared__ float Bs[2][BK][BN];

    int tid = threadIdx.x;
    int tx = tid % TX, ty = tid / TX;
    int m0 = blockIdx.y * BM, n0 = blockIdx.x * BN;
    int kstart = blockIdx.z * kchunk;
    int kend = min(K, kstart + kchunk);
    int ntiles = (kend - kstart) / BK;

    float4 aR[LA], bR[LB];

    auto loadA = [&](int kt) {
#pragma unroll
        for (int i = 0; i < LA; i++) {
            int f = tid + i * 256;
            int r = f / KQ, kq = (f % KQ) * 4;
            int m = m0 + r;
            aR[i] = (m < M)
                ? *(const float4*)(A + (size_t)m * lda + kstart + kt * BK + kq)
                : make_float4(0.f, 0.f, 0.f, 0.f);
        }
    };
    auto loadB = [&](int kt) {
#pragma unroll
        for (int i = 0; i < LB; i++) {
            int f = tid + i * 256;
            int r = f / KQ, kq = (f % KQ) * 4;
            int n = n0 + r;
            bR[i] = (n < N)
                ? *(const float4*)(B + (size_t)n * ldb + kstart + kt * BK + kq)
                : make_float4(0.f, 0.f, 0.f, 0.f);
        }
    };
    auto storeA = [&](int buf) {
#pragma unroll
        for (int i = 0; i < LA; i++) {
            int f = tid + i * 256;
            int r = f / KQ, kq = (f % KQ) * 4;
            As[buf][kq + 0][r] = aR[i].x; As[buf][kq + 1][r] = aR[i].y;
            As[buf][kq + 2][r] = aR[i].z; As[buf][kq + 3][r] = aR[i].w;
        }
    };
    auto storeB = [&](int buf) {
#pragma unroll
        for (int i = 0; i < LB; i++) {
            int f = tid + i * 256;
            int r = f / KQ, kq = (f % KQ) * 4;
            Bs[buf][kq + 0][r] = bR[i].x; Bs[buf][kq + 1][r] = bR[i].y;
            Bs[buf][kq + 2][r] = bR[i].z; Bs[buf][kq + 3][r] = bR[i].w;
        }
    };

    float acc[TM][TN];
#pragma unroll
    for (int i = 0; i < TM; i++)
#pragma unroll
        for (int j = 0; j < TN; j++) acc[i][j] = 0.f;

    loadA(0); loadB(0);
    storeA(0); storeB(0);
    __syncthreads();

    int buf = 0;
    for (int t = 0; t < ntiles; t++) {
        if (t + 1 < ntiles) { loadA(t + 1); loadB(t + 1); }
#pragma unroll
        for (int kk = 0; kk < BK; kk++) {
            float a[TM], b[TN];
#pragma unroll
            for (int i = 0; i < TM; i += 2) {
                float2 v2 = *(const float2*)&As[buf][kk][ty * TM + i];
                a[i] = v2.x; a[i + 1] = v2.y;
            }
#pragma unroll
            for (int j = 0; j < TN; j += 4) {
                float4 v4 = *(const float4*)&Bs[buf][kk][tx * TN + j];
                b[j] = v4.x; b[j + 1] = v4.y; b[j + 2] = v4.z; b[j + 3] = v4.w;
            }
#pragma unroll
            for (int i = 0; i < TM; i++)
#pragma unroll
                for (int j = 0; j < TN; j++) acc[i][j] += a[i] * b[j];
        }
        if (t + 1 < ntiles) {
            storeA(buf ^ 1); storeB(buf ^ 1);
            __syncthreads();
            buf ^= 1;
        }
    }

    float* Cb = C + (long long)blockIdx.z * partStride;
#pragma unroll
    for (int i = 0; i < TM; i++) {
        int m = m0 + ty * TM + i;
        if (m >= M) continue;
#pragma unroll
        for (int j = 0; j < TN; j++) {
            int n = n0 + tx * TN + j;
            if (n < N) Cb[(size_t)m * ldc + n] = acc[i][j];
        }
    }
}

// deterministic split-K reduction: dst[i] = sum_p src[p*len + i]
__global__ void reduce_parts(const float* __restrict__ src,
                             float* __restrict__ dst, int len, int parts) {
    int i = (blockIdx.x * blockDim.x + threadIdx.x) * 4;
    if (i >= len) return;
    float4 s = *(const float4*)(src + i);
    for (int p = 1; p < parts; p++) {
        float4 t = *(const float4*)(src + (size_t)p * len + i);
        s.x += t.x; s.y += t.y; s.z += t.z; s.w += t.w;
    }
    *(float4*)(dst + i) = s;
}

// ---------------------------------------------------------------------------
// geo[nk,h,w] = Gxy[nk,h] + Gxy[nk,64+w]
// ---------------------------------------------------------------------------
__global__ void __launch_bounds__(256)
assemble_kernel(float* __restrict__ outg)
{
    int nk = blockIdx.x;
    __shared__ float sx[HH];
    __shared__ float sy[WW];
    int tid = threadIdx.x;
    if (tid < 160) {
        float vv = g_gxy[nk * 160 + tid];
        if (tid < HH) sx[tid] = vv; else sy[tid - HH] = vv;
    }
    __syncthreads();

    float* base = outg + (size_t)nk * (HH * WW);
#pragma unroll
    for (int t = tid; t < (HH * WW) / 4; t += 256) {
        int h = t / 24;            // 96/4 = 24 float4 per row
        int w4 = (t % 24) * 4;
        float gx = sx[h];
        float4 v = make_float4(gx + sy[w4 + 0], gx + sy[w4 + 1],
                               gx + sy[w4 + 2], gx + sy[w4 + 3]);
        *(float4*)(base + h * WW + w4) = v;
    }
}

__global__ void indices_kernel(const float* __restrict__ rois, void* d_out, int mode) {
    int i = threadIdx.x;
    if (i >= N_ROIS) return;
    long long v = (long long)rois[i * 5];
    if (mode == 1)       ((float*)d_out)[i] = (float)v;
    else if (mode == 2)  ((long long*)d_out)[i] = v;
}

// ---------------------------------------------------------------------------
extern "C" void kernel_launch(void* const* d_in, const int* in_sizes, int n_in,
                              void* d_out, int out_size)
{
    const float* rois  = (const float*)d_in[1];
    const float* V_box = (const float*)d_in[2];
    const float* W_box = (const float*)d_in[3];
    const float* W_im  = (const float*)d_in[4];

    float *eps, *ex, *ey, *v, *box, *imgxy, *gxy, *partA, *partB;
    cudaGetSymbolAddress((void**)&eps,   g_eps);
    cudaGetSymbolAddress((void**)&ex,    g_ex);
    cudaGetSymbolAddress((void**)&ey,    g_ey);
    cudaGetSymbolAddress((void**)&v,     g_v);
    cudaGetSymbolAddress((void**)&box,   g_box);
    cudaGetSymbolAddress((void**)&imgxy, g_imgxy);
    cudaGetSymbolAddress((void**)&gxy,   g_gxy);
    cudaGetSymbolAddress((void**)&partA, g_partA);
    cudaGetSymbolAddress((void**)&partB, g_partB);

    long long extra = (long long)out_size - GEO_SIZE;
    int mode = (extra == 128) ? 1 : (extra == 256 ? 2 : 0);
    float* outg = (float*)d_out + (extra > 0 ? extra : 0);

    // 1) embeddings
    emb_rois_kernel<<<(N_ROIS * 2048 + 255) / 256, 256>>>(rois);
    emb_range_kernel<<<(HH * CEMB + 255) / 256, 256>>>(0);
    emb_range_kernel<<<(WW * CEMB + 255) / 256, 256>>>(1);

    // 2) v = eps @ V_box^T   [128,512] K=2048, split-K x8 -> 128 blocks
    gemm_tpl<64, 64, 32, 4, 4><<<dim3(8, 2, 8), 256>>>(
        eps, 2048, V_box, 2048, partA, 512, (long long)N_ROIS * CEMB,
        N_ROIS, CEMB, 2048, 256);
    reduce_parts<<<(N_ROIS * CEMB / 4 + 255) / 256, 256>>>(partA, v, N_ROIS * CEMB, 8);

    // 3) imgx = ex @ W_im[:, :512]^T  [64,256];  imgy = ey @ W_im[:,512:]^T [96,256]
    //    split-K x2, packed into imgxy[160,256]
    gemm_tpl<32, 64, 32, 2, 4><<<dim3(4, 2, 2), 256>>>(
        ex, CEMB, W_im, 1024, partB, 256, 160 * 256, HH, 256, 512, 256);
    gemm_tpl<32, 64, 32, 2, 4><<<dim3(4, 3, 2), 256>>>(
        ey, CEMB, W_im + 512, 1024, partB + HH * 256, 256, 160 * 256, WW, 256, 512, 256);
    reduce_parts<<<(160 * 256 / 4 + 255) / 256, 256>>>(partB, imgxy, 160 * 256, 2);

    // 4) box = v @ W_box^T   [128,12544] K=512  (dominant, 196 blocks)
    gemm_tpl<128, 64, 16, 8, 4><<<dim3(KO / 64, 1, 1), 256>>>(
        v, 512, W_box, 512, box, KO, 0, N_ROIS, KO, 512, 512);

    // 5) Gxy = box @ imgxy^T  [6272,160] K=256  (147 blocks = 1 wave)
    gemm_tpl<128, 64, 16, 8, 4><<<dim3(3, NK / 128, 1), 256>>>(
        box, 256, imgxy, 256, gxy, 160, 0, NK, 160, 256, 256);

    // 6) indices + broadcast-add assembly
    if (mode) indices_kernel<<<1, 128>>>(rois, d_out, mode);
    assemble_kernel<<<NK, 256>>>(outg);
}

// round 6
// speedup vs baseline: 2.7818x; 1.5175x over previous
#include <cuda_runtime.h>
#include <cuda_bf16.h>
#include <cstdint>

// ---------------------------------------------------------------------------
// GeometricTerm: algebraic collapse + HMMA (mma.sync bf16x3) big GEMMs.
//   geo[nk,h,w] = Gx[nk,h] + Gy[nk,w]
//   v   = eps @ V_box^T            (SIMT split-K)
//   box = v @ W_box^T              (mma.sync m16n8k16, bf16 hi/lo x3)
//   Gxy = box @ [imgx;imgy]^T      (mma.sync m16n8k16, bf16 hi/lo x3)
// NOTE: harness compiles at target sm_100 (no 'a') -> tcgen05 unavailable;
// mma.sync/ldmatrix are baseline-ISA and legal.
// ---------------------------------------------------------------------------

#define N_ROIS 128
#define CEMB   512
#define HH     64
#define WW     96
#define KO     12544
#define NK     6272
#define GEO_SIZE 38535168ll

__device__ float g_eps  [N_ROIS * 2048];
__device__ float g_ex   [HH * CEMB];
__device__ float g_ey   [WW * CEMB];
__device__ float g_partA[16 * N_ROIS * CEMB];
__device__ float g_partB[2 * 160 * 256];
__device__ __nv_bfloat16 g_vhi[N_ROIS * CEMB], g_vlo[N_ROIS * CEMB];
__device__ __nv_bfloat16 g_ihi[160 * 256],     g_ilo[160 * 256];
__device__ __nv_bfloat16 g_bhi[NK * 256],      g_blo[NK * 256];
__device__ float g_gxy[NK * 160];

// ---------------------------------------------------------------------------
// helpers
// ---------------------------------------------------------------------------
__device__ __forceinline__ uint32_t smem_u32(const void* p) {
    uint32_t a;
    asm("{ .reg .u64 t; cvta.to.shared.u64 t, %1; cvt.u32.u64 %0, t; }"
        : "=r"(a) : "l"(p));
    return a;
}
#define SWZ128(x) ((x) ^ (((x) >> 3) & 0x70))

#define LDSM4(r, a) \
    asm volatile("ldmatrix.sync.aligned.m8n8.x4.shared.b16 {%0,%1,%2,%3}, [%4];" \
        : "=r"((r)[0]), "=r"((r)[1]), "=r"((r)[2]), "=r"((r)[3]) : "r"(a))

__device__ __forceinline__ void mma_bf16(float* d, const uint32_t* a, const uint32_t* b) {
    asm volatile("mma.sync.aligned.m16n8k16.row.col.f32.bf16.bf16.f32 "
        "{%0,%1,%2,%3}, {%4,%5,%6,%7}, {%8,%9}, {%0,%1,%2,%3};"
        : "+f"(d[0]), "+f"(d[1]), "+f"(d[2]), "+f"(d[3])
        : "r"(a[0]), "r"(a[1]), "r"(a[2]), "r"(a[3]), "r"(b[0]), "r"(b[1]));
}

// split fp32 pair -> packed bf16 hi and lo words
__device__ __forceinline__ void split2(float a, float b, uint32_t& hi, uint32_t& lo) {
    __nv_bfloat16 ha = __float2bfloat16(a), hb = __float2bfloat16(b);
    __nv_bfloat16 la = __float2bfloat16(a - __bfloat162float(ha));
    __nv_bfloat16 lb = __float2bfloat16(b - __bfloat162float(hb));
    hi = (uint32_t)__bfloat16_as_ushort(ha) | ((uint32_t)__bfloat16_as_ushort(hb) << 16);
    lo = (uint32_t)__bfloat16_as_ushort(la) | ((uint32_t)__bfloat16_as_ushort(lb) << 16);
}

// ---------------------------------------------------------------------------
// embeddings (fp64 internally for fidelity vs JAX fp32 ref)
// ---------------------------------------------------------------------------
__device__ __forceinline__ float emb_val(float z, int i) {
    const double LOG1000_OVER_C = 6.907755278982137 / 512.0;
    double e = (i < 256) ? (double)(2 * i + 1) : (double)(2 * (i - 256));
    double a = (double)z / exp(e * LOG1000_OVER_C);
    return (i < 256) ? (float)sin(a) : (float)cos(a);
}
__global__ void emb_rois_kernel(const float* __restrict__ rois) {
    int idx = blockIdx.x * blockDim.x + threadIdx.x;
    if (idx >= N_ROIS * 2048) return;
    int n = idx >> 11, d = idx & 2047;
    g_eps[idx] = emb_val(rois[n * 5 + 1 + (d >> 9)], d & 511);
}
__global__ void emb_range_kernel(int which) {
    int idx = blockIdx.x * blockDim.x + threadIdx.x;
    int rows = which ? WW : HH;
    if (idx >= rows * CEMB) return;
    (which ? g_ey : g_ex)[idx] = emb_val((float)(idx >> 9), idx & 511);
}

// ---------------------------------------------------------------------------
// SIMT split-K SGEMM (small v/img GEMMs)
// ---------------------------------------------------------------------------
template<int BM, int BN, int BK, int TM, int TN>
__global__ void __launch_bounds__(256)
gemm_tpl(const float* __restrict__ A, int lda,
         const float* __restrict__ B, int ldb,
         float* __restrict__ C, int ldc, long long partStride,
         int M, int N, int K, int kchunk)
{
    constexpr int TX = BN / TN;
    constexpr int TY = BM / TM;
    static_assert(TX * TY == 256, "thread shape");
    constexpr int LA = BM * BK / 1024;
    constexpr int LB = BN * BK / 1024;
    constexpr int KQ = BK / 4;

    __shared__ float As[2][BK][BM];
    __shared__ float Bs[2][BK][BN];

    int tid = threadIdx.x;
    int tx = tid % TX, ty = tid / TX;
    int m0 = blockIdx.y * BM, n0 = blockIdx.x * BN;
    int kstart = blockIdx.z * kchunk;
    int ntiles = (min(K, kstart + kchunk) - kstart) / BK;

    float4 aR[LA], bR[LB];
    auto loadA = [&](int kt) {
#pragma unroll
        for (int i = 0; i < LA; i++) {
            int f = tid + i * 256, r = f / KQ, kq = (f % KQ) * 4;
            int m = m0 + r;
            aR[i] = (m < M) ? *(const float4*)(A + (size_t)m * lda + kstart + kt * BK + kq)
                            : make_float4(0.f, 0.f, 0.f, 0.f);
        }
    };
    auto loadB = [&](int kt) {
#pragma unroll
        for (int i = 0; i < LB; i++) {
            int f = tid + i * 256, r = f / KQ, kq = (f % KQ) * 4;
            int n = n0 + r;
            bR[i] = (n < N) ? *(const float4*)(B + (size_t)n * ldb + kstart + kt * BK + kq)
                            : make_float4(0.f, 0.f, 0.f, 0.f);
        }
    };
    auto storeA = [&](int buf) {
#pragma unroll
        for (int i = 0; i < LA; i++) {
            int f = tid + i * 256, r = f / KQ, kq = (f % KQ) * 4;
            As[buf][kq + 0][r] = aR[i].x; As[buf][kq + 1][r] = aR[i].y;
            As[buf][kq + 2][r] = aR[i].z; As[buf][kq + 3][r] = aR[i].w;
        }
    };
    auto storeB = [&](int buf) {
#pragma unroll
        for (int i = 0; i < LB; i++) {
            int f = tid + i * 256, r = f / KQ, kq = (f % KQ) * 4;
            Bs[buf][kq + 0][r] = bR[i].x; Bs[buf][kq + 1][r] = bR[i].y;
            Bs[buf][kq + 2][r] = bR[i].z; Bs[buf][kq + 3][r] = bR[i].w;
        }
    };

    float acc[TM][TN];
#pragma unroll
    for (int i = 0; i < TM; i++)
#pragma unroll
        for (int j = 0; j < TN; j++) acc[i][j] = 0.f;

    loadA(0); loadB(0); storeA(0); storeB(0);
    __syncthreads();

    int buf = 0;
    for (int t = 0; t < ntiles; t++) {
        if (t + 1 < ntiles) { loadA(t + 1); loadB(t + 1); }
#pragma unroll
        for (int kk = 0; kk < BK; kk++) {
            float a[TM], b[TN];
#pragma unroll
            for (int i = 0; i < TM; i += 2) {
                float2 v2 = *(const float2*)&As[buf][kk][ty * TM + i];
                a[i] = v2.x; a[i + 1] = v2.y;
            }
#pragma unroll
            for (int j = 0; j < TN; j += 4) {
                float4 v4 = *(const float4*)&Bs[buf][kk][tx * TN + j];
                b[j] = v4.x; b[j + 1] = v4.y; b[j + 2] = v4.z; b[j + 3] = v4.w;
            }
#pragma unroll
            for (int i = 0; i < TM; i++)
#pragma unroll
                for (int j = 0; j < TN; j++) acc[i][j] += a[i] * b[j];
        }
        if (t + 1 < ntiles) {
            storeA(buf ^ 1); storeB(buf ^ 1);
            __syncthreads();
            buf ^= 1;
        }
    }

    float* Cb = C + (long long)blockIdx.z * partStride;
#pragma unroll
    for (int i = 0; i < TM; i++) {
        int m = m0 + ty * TM + i;
        if (m >= M) continue;
#pragma unroll
        for (int j = 0; j < TN; j++) {
            int n = n0 + tx * TN + j;
            if (n < N) Cb[(size_t)m * ldc + n] = acc[i][j];
        }
    }
}

// split-K reductions emitting bf16 hi/lo
__global__ void reduce_v_kernel() {
    int i = blockIdx.x * blockDim.x + threadIdx.x;
    if (i >= N_ROIS * CEMB) return;
    float s = 0.f;
#pragma unroll
    for (int p = 0; p < 16; p++) s += g_partA[p * (N_ROIS * CEMB) + i];
    __nv_bfloat16 h = __float2bfloat16(s);
    g_vhi[i] = h;
    g_vlo[i] = __float2bfloat16(s - __bfloat162float(h));
}
__global__ void reduce_img_kernel() {
    int i = blockIdx.x * blockDim.x + threadIdx.x;
    if (i >= 160 * 256) return;
    float s = g_partB[i] + g_partB[160 * 256 + i];
    __nv_bfloat16 h = __float2bfloat16(s);
    g_ihi[i] = h;
    g_ilo[i] = __float2bfloat16(s - __bfloat162float(h));
}

// ---------------------------------------------------------------------------
// HMMA box GEMM: C[128, 12544] = v @ W_box^T, K=512.
// 196 blocks of [128 M x 64 N]; BK=64; 8 warps (4M x 2N), warp tile 32x32.
// SW128 smem (128B rows, conflict-free ldmatrix). Epilogue -> bf16 hi/lo.
// buf layout (49152B): Ahi 16K | Alo 16K | Bhi 8K | Blo 8K.  2 bufs = 96K.
// ---------------------------------------------------------------------------
#define BOXB 49152
__global__ void __launch_bounds__(256)
hmma_box(const float* __restrict__ Wbox)
{
    extern __shared__ __align__(1024) char smem[];
    uint32_t sbase = smem_u32(smem);
    int tid = threadIdx.x, w = tid >> 5, l = tid & 31;
    int n0 = blockIdx.x * 64;
    int kcta = n0 >> 8, o0 = n0 & 255;
    int wm = (w >> 1) * 32, wn = (w & 1) * 32;

    uint4 aR[8];        // A hi[0..3], lo[4..7]
    float4 bRf[4];
    auto loadg = [&](int t) {
        int k0 = t * 64;
#pragma unroll
        for (int i = 0; i < 4; i++) {
            int s = tid + i * 256, r = s >> 3, c = s & 7;
            size_t eo = (size_t)r * 512 + k0 + c * 8;
            aR[i]     = *(const uint4*)(g_vhi + eo);
            aR[i + 4] = *(const uint4*)(g_vlo + eo);
        }
#pragma unroll
        for (int i = 0; i < 2; i++) {
            int s = tid + i * 256, r = s >> 3, c = s & 7;
            const float* src = Wbox + (size_t)(n0 + r) * 512 + k0 + c * 8;
            bRf[2 * i]     = *(const float4*)src;
            bRf[2 * i + 1] = *(const float4*)(src + 4);
        }
    };
    auto storeb = [&](int buf) {
        char* base = smem + buf * BOXB;
#pragma unroll
        for (int i = 0; i < 4; i++) {
            int s = tid + i * 256, r = s >> 3, c = s & 7;
            uint32_t off = SWZ128((uint32_t)(r * 128 + c * 16));
            *(uint4*)(base + off)         = aR[i];
            *(uint4*)(base + 16384 + off) = aR[i + 4];
        }
#pragma unroll
        for (int i = 0; i < 2; i++) {
            int s = tid + i * 256, r = s >> 3, c = s & 7;
            float fv[8] = {bRf[2*i].x, bRf[2*i].y, bRf[2*i].z, bRf[2*i].w,
                           bRf[2*i+1].x, bRf[2*i+1].y, bRf[2*i+1].z, bRf[2*i+1].w};
            uint4 h4, l4;
            split2(fv[0], fv[1], h4.x, l4.x); split2(fv[2], fv[3], h4.y, l4.y);
            split2(fv[4], fv[5], h4.z, l4.z); split2(fv[6], fv[7], h4.w, l4.w);
            uint32_t off = SWZ128((uint32_t)(r * 128 + c * 16));
            *(uint4*)(base + 32768 + off) = h4;
            *(uint4*)(base + 40960 + off) = l4;
        }
    };

    float acc[2][4][4];
#pragma unroll
    for (int s = 0; s < 2; s++)
#pragma unroll
        for (int j = 0; j < 4; j++)
#pragma unroll
            for (int q = 0; q < 4; q++) acc[s][j][q] = 0.f;

    loadg(0); storeb(0);
    __syncthreads();

    for (int t = 0; t < 8; t++) {
        int buf = t & 1;
        if (t + 1 < 8) loadg(t + 1);
        uint32_t B0 = sbase + buf * BOXB;
#pragma unroll
        for (int kk = 0; kk < 4; kk++) {
            uint32_t ah[2][4], al[2][4];
#pragma unroll
            for (int s = 0; s < 2; s++) {
                int row = wm + s * 16 + (l & 15);
                int ch = kk * 2 + (l >> 4);
                uint32_t off = SWZ128((uint32_t)(row * 128 + ch * 16));
                LDSM4(ah[s], B0 + off);
                LDSM4(al[s], B0 + 16384 + off);
            }
#pragma unroll
            for (int p = 0; p < 2; p++) {
                int nrow = wn + p * 16 + (l & 7) + ((l >> 4) << 3);
                int ch = kk * 2 + ((l >> 3) & 1);
                uint32_t off = SWZ128((uint32_t)(nrow * 128 + ch * 16));
                uint32_t bh[4], bl[4];
                LDSM4(bh, B0 + 32768 + off);
                LDSM4(bl, B0 + 40960 + off);
#pragma unroll
                for (int s = 0; s < 2; s++) {
                    mma_bf16(acc[s][2*p],     ah[s], bh);
                    mma_bf16(acc[s][2*p],     ah[s], bl);
                    mma_bf16(acc[s][2*p],     al[s], bh);
                    mma_bf16(acc[s][2*p + 1], ah[s], bh + 2);
                    mma_bf16(acc[s][2*p + 1], ah[s], bl + 2);
                    mma_bf16(acc[s][2*p + 1], al[s], bh + 2);
                }
            }
        }
        if (t + 1 < 8) {
            storeb(buf ^ 1);
            __syncthreads();
        }
    }

    // epilogue -> g_bhi/g_blo[(m*49 + kcta)*256 + o]
#pragma unroll
    for (int s = 0; s < 2; s++) {
        int m = wm + s * 16 + (l >> 2);
#pragma unroll
        for (int j = 0; j < 4; j++) {
            int o = o0 + wn + j * 8 + (l & 3) * 2;
            uint32_t hi, lo;
            split2(acc[s][j][0], acc[s][j][1], hi, lo);
            size_t b0 = (size_t)(m * 49 + kcta) * 256 + o;
            *(uint32_t*)(g_bhi + b0) = hi;
            *(uint32_t*)(g_blo + b0) = lo;
            split2(acc[s][j][2], acc[s][j][3], hi, lo);
            size_t b1 = (size_t)((m + 8) * 49 + kcta) * 256 + o;
            *(uint32_t*)(g_bhi + b1) = hi;
            *(uint32_t*)(g_blo + b1) = lo;
        }
    }
}

// ---------------------------------------------------------------------------
// HMMA Gxy GEMM: C[6272, 160] = box @ imgxy^T, K=256.
// 98 blocks of [64 M x 160 N]; BK=64; 8 warps (4M x 2N), warp tile 16x80.
// buf layout (57344B): Ahi 8K | Alo 8K | Bhi 20K | Blo 20K.  2 bufs = 112K.
// ---------------------------------------------------------------------------
#define GXYB 57344
__global__ void __launch_bounds__(256)
hmma_gxy()
{
    extern __shared__ __align__(1024) char smem[];
    uint32_t sbase = smem_u32(smem);
    int tid = threadIdx.x, w = tid >> 5, l = tid & 31;
    int m0 = blockIdx.x * 64;
    int wm = (w >> 1) * 16, wn = (w & 1) * 80;

    uint4 aR[4], bR[10];
    auto loadg = [&](int t) {
        int k0 = t * 64;
#pragma unroll
        for (int i = 0; i < 2; i++) {
            int s = tid + i * 256, r = s >> 3, c = s & 7;
            size_t eo = (size_t)(m0 + r) * 256 + k0 + c * 8;
            aR[i]     = *(const uint4*)(g_bhi + eo);
            aR[i + 2] = *(const uint4*)(g_blo + eo);
        }
#pragma unroll
        for (int i = 0; i < 5; i++) {
            int s = tid + i * 256, r = s >> 3, c = s & 7;
            size_t eo = (size_t)r * 256 + k0 + c * 8;
            bR[i]     = *(const uint4*)(g_ihi + eo);
            bR[i + 5] = *(const uint4*)(g_ilo + eo);
        }
    };
    auto storeb = [&](int buf) {
        char* base = smem + buf * GXYB;
#pragma unroll
        for (int i = 0; i < 2; i++) {
            int s = tid + i * 256, r = s >> 3, c = s & 7;
            uint32_t off = SWZ128((uint32_t)(r * 128 + c * 16));
            *(uint4*)(base + off)        = aR[i];
            *(uint4*)(base + 8192 + off) = aR[i + 2];
        }
#pragma unroll
        for (int i = 0; i < 5; i++) {
            int s = tid + i * 256, r = s >> 3, c = s & 7;
            uint32_t off = SWZ128((uint32_t)(r * 128 + c * 16));
            *(uint4*)(base + 16384 + off) = bR[i];
            *(uint4*)(base + 36864 + off) = bR[i + 5];
        }
    };

    float acc[10][4];
#pragma unroll
    for (int j = 0; j < 10; j++)
#pragma unroll
        for (int q = 0; q < 4; q++) acc[j][q] = 0.f;

    loadg(0); storeb(0);
    __syncthreads();

    for (int t = 0; t < 4; t++) {
        int buf = t & 1;
        if (t + 1 < 4) loadg(t + 1);
        uint32_t B0 = sbase + buf * GXYB;
#pragma unroll
        for (int kk = 0; kk < 4; kk++) {
            uint32_t ah[4], al[4];
            {
                int row = wm + (l & 15);
                int ch = kk * 2 + (l >> 4);
                uint32_t off = SWZ128((uint32_t)(row * 128 + ch * 16));
                LDSM4(ah, B0 + off);
                LDSM4(al, B0 + 8192 + off);
            }
#pragma unroll
            for (int p = 0; p < 5; p++) {
                int nrow = wn + p * 16 + (l & 7) + ((l >> 4) << 3);
                int ch = kk * 2 + ((l >> 3) & 1);
                uint32_t off = SWZ128((uint32_t)(nrow * 128 + ch * 16));
                uint32_t bh[4], bl[4];
                LDSM4(bh, B0 + 16384 + off);
                LDSM4(bl, B0 + 36864 + off);
                mma_bf16(acc[2*p],     ah, bh);
                mma_bf16(acc[2*p],     ah, bl);
                mma_bf16(acc[2*p],     al, bh);
                mma_bf16(acc[2*p + 1], ah, bh + 2);
                mma_bf16(acc[2*p + 1], ah, bl + 2);
                mma_bf16(acc[2*p + 1], al, bh + 2);
            }
        }
        if (t + 1 < 4) {
            storeb(buf ^ 1);
            __syncthreads();
        }
    }

    int row = m0 + wm + (l >> 2);
#pragma unroll
    for (int j = 0; j < 10; j++) {
        int col = wn + j * 8 + (l & 3) * 2;
        *(float2*)(g_gxy + (size_t)row * 160 + col) =
            make_float2(acc[j][0], acc[j][1]);
        *(float2*)(g_gxy + (size_t)(row + 8) * 160 + col) =
            make_float2(acc[j][2], acc[j][3]);
    }
}

// ---------------------------------------------------------------------------
// geo[nk,h,w] = Gxy[nk,h] + Gxy[nk,64+w]
// ---------------------------------------------------------------------------
__global__ void __launch_bounds__(256)
assemble_kernel(float* __restrict__ outg)
{
    int nk = blockIdx.x;
    __shared__ float sx[HH];
    __shared__ float sy[WW];
    int tid = threadIdx.x;
    if (tid < 160) {
        float vv = g_gxy[nk * 160 + tid];
        if (tid < HH) sx[tid] = vv; else sy[tid - HH] = vv;
    }
    __syncthreads();

    float* base = outg + (size_t)nk * (HH * WW);
#pragma unroll
    for (int t = tid; t < (HH * WW) / 4; t += 256) {
        int h = t / 24;
        int w4 = (t % 24) * 4;
        float gx = sx[h];
        float4 v = make_float4(gx + sy[w4 + 0], gx + sy[w4 + 1],
                               gx + sy[w4 + 2], gx + sy[w4 + 3]);
        *(float4*)(base + h * WW + w4) = v;
    }
}

__global__ void indices_kernel(const float* __restrict__ rois, void* d_out, int mode) {
    int i = threadIdx.x;
    if (i >= N_ROIS) return;
    long long v = (long long)rois[i * 5];
    if (mode == 1)       ((float*)d_out)[i] = (float)v;
    else if (mode == 2)  ((long long*)d_out)[i] = v;
}

// ---------------------------------------------------------------------------
extern "C" void kernel_launch(void* const* d_in, const int* in_sizes, int n_in,
                              void* d_out, int out_size)
{
    const float* rois  = (const float*)d_in[1];
    const float* V_box = (const float*)d_in[2];
    const float* W_box = (const float*)d_in[3];
    const float* W_im  = (const float*)d_in[4];

    float *eps, *ex, *ey, *partA, *partB;
    cudaGetSymbolAddress((void**)&eps,   g_eps);
    cudaGetSymbolAddress((void**)&ex,    g_ex);
    cudaGetSymbolAddress((void**)&ey,    g_ey);
    cudaGetSymbolAddress((void**)&partA, g_partA);
    cudaGetSymbolAddress((void**)&partB, g_partB);

    cudaFuncSetAttribute(hmma_box, cudaFuncAttributeMaxDynamicSharedMemorySize, 2 * BOXB);
    cudaFuncSetAttribute(hmma_gxy, cudaFuncAttributeMaxDynamicSharedMemorySize, 2 * GXYB);

    long long extra = (long long)out_size - GEO_SIZE;
    int mode = (extra == 128) ? 1 : (extra == 256 ? 2 : 0);
    float* outg = (float*)d_out + (extra > 0 ? extra : 0);

    // 1) embeddings
    emb_rois_kernel<<<(N_ROIS * 2048 + 255) / 256, 256>>>(rois);
    emb_range_kernel<<<(HH * CEMB + 255) / 256, 256>>>(0);
    emb_range_kernel<<<(WW * CEMB + 255) / 256, 256>>>(1);

    // 2) v = eps @ V_box^T  [128,512] K=2048, split-K x16
    gemm_tpl<64, 64, 32, 4, 4><<<dim3(8, 2, 16), 256>>>(
        eps, 2048, V_box, 2048, partA, 512, (long long)N_ROIS * CEMB,
        N_ROIS, CEMB, 2048, 128);
    reduce_v_kernel<<<(N_ROIS * CEMB + 255) / 256, 256>>>();

    // 3) imgx/imgy (split-K x2) -> imgxy hi/lo [160,256]
    gemm_tpl<32, 64, 32, 2, 4><<<dim3(4, 2, 2), 256>>>(
        ex, CEMB, W_im, 1024, partB, 256, 160 * 256, HH, 256, 512, 256);
    gemm_tpl<32, 64, 32, 2, 4><<<dim3(4, 3, 2), 256>>>(
        ey, CEMB, W_im + 512, 1024, partB + HH * 256, 256, 160 * 256, WW, 256, 512, 256);
    reduce_img_kernel<<<(160 * 256 + 255) / 256, 256>>>();

    // 4) box = v @ W_box^T  (HMMA bf16x3), emits box hi/lo bf16
    hmma_box<<<196, 256, 2 * BOXB>>>(W_box);

    // 5) Gxy = box @ imgxy^T  (HMMA bf16x3)
    hmma_gxy<<<98, 256, 2 * GXYB>>>();

    // 6) indices + broadcast-add assembly
    if (mode) indices_kernel<<<1, 128>>>(rois, d_out, mode);
    assemble_kernel<<<NK, 256>>>(outg);
}

// round 7
// speedup vs baseline: 2.9714x; 1.0682x over previous
#include <cuda_runtime.h>
#include <cuda_bf16.h>
#include <cstdint>

// ---------------------------------------------------------------------------
// GeometricTerm: algebraic collapse + HMMA (mma.sync bf16x3) GEMM chain.
//   geo[nk,h,w] = Gx[nk,h] + Gy[nk,w]
//   v   = eps @ V_box^T            (HMMA bf16x3, split-K x8)
//   box = v @ W_box^T              (HMMA bf16x3)
//   Gxy = box @ [imgx;imgy]^T      (HMMA bf16x3)
// Embeddings: fp64 only for a 512-entry invden table; per-element fp32 sinf.
// ---------------------------------------------------------------------------

#define N_ROIS 128
#define CEMB   512
#define HH     64
#define WW     96
#define KO     12544
#define NK     6272
#define GEO_SIZE 38535168ll

__device__ float g_invden[512];
__device__ __nv_bfloat16 g_ehi[N_ROIS * 2048], g_elo[N_ROIS * 2048];
__device__ float g_ex   [HH * CEMB];
__device__ float g_ey   [WW * CEMB];
__device__ float g_partA[8 * N_ROIS * CEMB];
__device__ float g_partB[2 * 160 * 256];
__device__ __nv_bfloat16 g_vhi[N_ROIS * CEMB], g_vlo[N_ROIS * CEMB];
__device__ __nv_bfloat16 g_ihi[160 * 256],     g_ilo[160 * 256];
__device__ __nv_bfloat16 g_bhi[NK * 256],      g_blo[NK * 256];
__device__ float g_gxy[NK * 160];

// ---------------------------------------------------------------------------
// helpers
// ---------------------------------------------------------------------------
__device__ __forceinline__ uint32_t smem_u32(const void* p) {
    uint32_t a;
    asm("{ .reg .u64 t; cvta.to.shared.u64 t, %1; cvt.u32.u64 %0, t; }"
        : "=r"(a) : "l"(p));
    return a;
}
#define SWZ128(x) ((x) ^ (((x) >> 3) & 0x70))

#define LDSM4(r, a) \
    asm volatile("ldmatrix.sync.aligned.m8n8.x4.shared.b16 {%0,%1,%2,%3}, [%4];" \
        : "=r"((r)[0]), "=r"((r)[1]), "=r"((r)[2]), "=r"((r)[3]) : "r"(a))

__device__ __forceinline__ void mma_bf16(float* d, const uint32_t* a, const uint32_t* b) {
    asm volatile("mma.sync.aligned.m16n8k16.row.col.f32.bf16.bf16.f32 "
        "{%0,%1,%2,%3}, {%4,%5,%6,%7}, {%8,%9}, {%0,%1,%2,%3};"
        : "+f"(d[0]), "+f"(d[1]), "+f"(d[2]), "+f"(d[3])
        : "r"(a[0]), "r"(a[1]), "r"(a[2]), "r"(a[3]), "r"(b[0]), "r"(b[1]));
}

__device__ __forceinline__ void split2(float a, float b, uint32_t& hi, uint32_t& lo) {
    __nv_bfloat16 ha = __float2bfloat16(a), hb = __float2bfloat16(b);
    __nv_bfloat16 la = __float2bfloat16(a - __bfloat162float(ha));
    __nv_bfloat16 lb = __float2bfloat16(b - __bfloat162float(hb));
    hi = (uint32_t)__bfloat16_as_ushort(ha) | ((uint32_t)__bfloat16_as_ushort(hb) << 16);
    lo = (uint32_t)__bfloat16_as_ushort(la) | ((uint32_t)__bfloat16_as_ushort(lb) << 16);
}

// ---------------------------------------------------------------------------
// embeddings: fp64 table once; then fp32 multiply + sinf/cosf
// ---------------------------------------------------------------------------
__global__ void table_kernel() {
    int i = blockIdx.x * blockDim.x + threadIdx.x;
    if (i >= 512) return;
    const double LOG1000_OVER_C = 6.907755278982137 / 512.0;
    double e = (i < 256) ? (double)(2 * i + 1) : (double)(2 * (i - 256));
    g_invden[i] = (float)exp(-e * LOG1000_OVER_C);
}

__device__ __forceinline__ float emb_f(float z, int i) {
    float a = z * g_invden[i];
    return (i < 256) ? sinf(a) : cosf(a);
}

// eps -> bf16 hi/lo directly (pairs of adjacent i)
__global__ void emb_rois_kernel(const float* __restrict__ rois) {
    int p = blockIdx.x * blockDim.x + threadIdx.x;
    if (p >= N_ROIS * 1024) return;
    int idx = p * 2;
    int n = idx >> 11, d = idx & 2047;
    int j = d >> 9, i = d & 511;
    float z = rois[n * 5 + 1 + j];
    float v0 = emb_f(z, i), v1 = emb_f(z, i + 1);
    uint32_t hi, lo;
    split2(v0, v1, hi, lo);
    *(uint32_t*)(g_ehi + idx) = hi;
    *(uint32_t*)(g_elo + idx) = lo;
}

// ex rows 0..63 (z=row), ey rows 64..159 (z=row-64), fp32
__global__ void emb_range_kernel() {
    int idx = blockIdx.x * blockDim.x + threadIdx.x;
    if (idx >= 160 * CEMB) return;
    int r = idx >> 9, i = idx & 511;
    float z = (float)(r < HH ? r : r - HH);
    float val = emb_f(z, i);
    if (r < HH) g_ex[r * CEMB + i] = val;
    else        g_ey[(r - HH) * CEMB + i] = val;
}

// ---------------------------------------------------------------------------
// SIMT split-K SGEMM (img GEMMs only)
// ---------------------------------------------------------------------------
template<int BM, int BN, int BK, int TM, int TN>
__global__ void __launch_bounds__(256)
gemm_tpl(const float* __restrict__ A, int lda,
         const float* __restrict__ B, int ldb,
         float* __restrict__ C, int ldc, long long partStride,
         int M, int N, int K, int kchunk)
{
    constexpr int TX = BN / TN;
    constexpr int TY = BM / TM;
    static_assert(TX * TY == 256, "thread shape");
    constexpr int LA = BM * BK / 1024;
    constexpr int LB = BN * BK / 1024;
    constexpr int KQ = BK / 4;

    __shared__ float As[2][BK][BM];
    __shared__ float Bs[2][BK][BN];

    int tid = threadIdx.x;
    int tx = tid % TX, ty = tid / TX;
    int m0 = blockIdx.y * BM, n0 = blockIdx.x * BN;
    int kstart = blockIdx.z * kchunk;
    int ntiles = (min(K, kstart + kchunk) - kstart) / BK;

    float4 aR[LA], bR[LB];
    auto loadA = [&](int kt) {
#pragma unroll
        for (int i = 0; i < LA; i++) {
            int f = tid + i * 256, r = f / KQ, kq = (f % KQ) * 4;
            int m = m0 + r;
            aR[i] = (m < M) ? *(const float4*)(A + (size_t)m * lda + kstart + kt * BK + kq)
                            : make_float4(0.f, 0.f, 0.f, 0.f);
        }
    };
    auto loadB = [&](int kt) {
#pragma unroll
        for (int i = 0; i < LB; i++) {
            int f = tid + i * 256, r = f / KQ, kq = (f % KQ) * 4;
            int n = n0 + r;
            bR[i] = (n < N) ? *(const float4*)(B + (size_t)n * ldb + kstart + kt * BK + kq)
                            : make_float4(0.f, 0.f, 0.f, 0.f);
        }
    };
    auto storeA = [&](int buf) {
#pragma unroll
        for (int i = 0; i < LA; i++) {
            int f = tid + i * 256, r = f / KQ, kq = (f % KQ) * 4;
            As[buf][kq + 0][r] = aR[i].x; As[buf][kq + 1][r] = aR[i].y;
            As[buf][kq + 2][r] = aR[i].z; As[buf][kq + 3][r] = aR[i].w;
        }
    };
    auto storeB = [&](int buf) {
#pragma unroll
        for (int i = 0; i < LB; i++) {
            int f = tid + i * 256, r = f / KQ, kq = (f % KQ) * 4;
            Bs[buf][kq + 0][r] = bR[i].x; Bs[buf][kq + 1][r] = bR[i].y;
            Bs[buf][kq + 2][r] = bR[i].z; Bs[buf][kq + 3][r] = bR[i].w;
        }
    };

    float acc[TM][TN];
#pragma unroll
    for (int i = 0; i < TM; i++)
#pragma unroll
        for (int j = 0; j < TN; j++) acc[i][j] = 0.f;

    loadA(0); loadB(0); storeA(0); storeB(0);
    __syncthreads();

    int buf = 0;
    for (int t = 0; t < ntiles; t++) {
        if (t + 1 < ntiles) { loadA(t + 1); loadB(t + 1); }
#pragma unroll
        for (int kk = 0; kk < BK; kk++) {
            float a[TM], b[TN];
#pragma unroll
            for (int i = 0; i < TM; i += 2) {
                float2 v2 = *(const float2*)&As[buf][kk][ty * TM + i];
                a[i] = v2.x; a[i + 1] = v2.y;
            }
#pragma unroll
            for (int j = 0; j < TN; j += 4) {
                float4 v4 = *(const float4*)&Bs[buf][kk][tx * TN + j];
                b[j] = v4.x; b[j + 1] = v4.y; b[j + 2] = v4.z; b[j + 3] = v4.w;
            }
#pragma unroll
            for (int i = 0; i < TM; i++)
#pragma unroll
                for (int j = 0; j < TN; j++) acc[i][j] += a[i] * b[j];
        }
        if (t + 1 < ntiles) {
            storeA(buf ^ 1); storeB(buf ^ 1);
            __syncthreads();
            buf ^= 1;
        }
    }

    float* Cb = C + (long long)blockIdx.z * partStride;
#pragma unroll
    for (int i = 0; i < TM; i++) {
        int m = m0 + ty * TM + i;
        if (m >= M) continue;
#pragma unroll
        for (int j = 0; j < TN; j++) {
            int n = n0 + tx * TN + j;
            if (n < N) Cb[(size_t)m * ldc + n] = acc[i][j];
        }
    }
}

// reductions emitting bf16 hi/lo
__global__ void reduce_v_kernel() {
    int i = blockIdx.x * blockDim.x + threadIdx.x;
    if (i >= N_ROIS * CEMB) return;
    float s = 0.f;
#pragma unroll
    for (int p = 0; p < 8; p++) s += g_partA[p * (N_ROIS * CEMB) + i];
    __nv_bfloat16 h = __float2bfloat16(s);
    g_vhi[i] = h;
    g_vlo[i] = __float2bfloat16(s - __bfloat162float(h));
}
__global__ void reduce_img_kernel() {
    int i = blockIdx.x * blockDim.x + threadIdx.x;
    if (i >= 160 * 256) return;
    float s = g_partB[i] + g_partB[160 * 256 + i];
    __nv_bfloat16 h = __float2bfloat16(s);
    g_ihi[i] = h;
    g_ilo[i] = __float2bfloat16(s - __bfloat162float(h));
}

// ---------------------------------------------------------------------------
// HMMA v GEMM: C[128,512] = eps @ V_box^T, K=2048, split-K x8.
// grid (8 Ntiles, 1, 8 Kchunks); tile 128M x 64N; BK=64 (4 iters/chunk).
// buf (49152B): Ahi 16K | Alo 16K | Bhi 8K | Blo 8K. Epilogue: fp32 partials.
// ---------------------------------------------------------------------------
#define BOXB 49152
__global__ void __launch_bounds__(256)
hmma_v(const float* __restrict__ Vbox)
{
    extern __shared__ __align__(1024) char smem[];
    uint32_t sbase = smem_u32(smem);
    int tid = threadIdx.x, w = tid >> 5, l = tid & 31;
    int n0 = blockIdx.x * 64;
    int kstart = blockIdx.z * 256;
    int wm = (w >> 1) * 32, wn = (w & 1) * 32;

    uint4 aR[8];
    float4 bRf[4];
    auto loadg = [&](int t) {
        int k0 = kstart + t * 64;
#pragma unroll
        for (int i = 0; i < 4; i++) {
            int s = tid + i * 256, r = s >> 3, c = s & 7;
            size_t eo = (size_t)r * 2048 + k0 + c * 8;
            aR[i]     = *(const uint4*)(g_ehi + eo);
            aR[i + 4] = *(const uint4*)(g_elo + eo);
        }
#pragma unroll
        for (int i = 0; i < 2; i++) {
            int s = tid + i * 256, r = s >> 3, c = s & 7;
            const float* src = Vbox + (size_t)(n0 + r) * 2048 + k0 + c * 8;
            bRf[2 * i]     = *(const float4*)src;
            bRf[2 * i + 1] = *(const float4*)(src + 4);
        }
    };
    auto storeb = [&](int buf) {
        char* base = smem + buf * BOXB;
#pragma unroll
        for (int i = 0; i < 4; i++) {
            int s = tid + i * 256, r = s >> 3, c = s & 7;
            uint32_t off = SWZ128((uint32_t)(r * 128 + c * 16));
            *(uint4*)(base + off)         = aR[i];
            *(uint4*)(base + 16384 + off) = aR[i + 4];
        }
#pragma unroll
        for (int i = 0; i < 2; i++) {
            int s = tid + i * 256, r = s >> 3, c = s & 7;
            float fv[8] = {bRf[2*i].x, bRf[2*i].y, bRf[2*i].z, bRf[2*i].w,
                           bRf[2*i+1].x, bRf[2*i+1].y, bRf[2*i+1].z, bRf[2*i+1].w};
            uint4 h4, l4;
            split2(fv[0], fv[1], h4.x, l4.x); split2(fv[2], fv[3], h4.y, l4.y);
            split2(fv[4], fv[5], h4.z, l4.z); split2(fv[6], fv[7], h4.w, l4.w);
            uint32_t off = SWZ128((uint32_t)(r * 128 + c * 16));
            *(uint4*)(base + 32768 + off) = h4;
            *(uint4*)(base + 40960 + off) = l4;
        }
    };

    float acc[2][4][4];
#pragma unroll
    for (int s = 0; s < 2; s++)
#pragma unroll
        for (int j = 0; j < 4; j++)
#pragma unroll
            for (int q = 0; q < 4; q++) acc[s][j][q] = 0.f;

    loadg(0); storeb(0);
    __syncthreads();

    for (int t = 0; t < 4; t++) {
        int buf = t & 1;
        if (t + 1 < 4) loadg(t + 1);
        uint32_t B0 = sbase + buf * BOXB;
#pragma unroll
        for (int kk = 0; kk < 4; kk++) {
            uint32_t ah[2][4], al[2][4];
#pragma unroll
            for (int s = 0; s < 2; s++) {
                int row = wm + s * 16 + (l & 15);
                int ch = kk * 2 + (l >> 4);
                uint32_t off = SWZ128((uint32_t)(row * 128 + ch * 16));
                LDSM4(ah[s], B0 + off);
                LDSM4(al[s], B0 + 16384 + off);
            }
#pragma unroll
            for (int p = 0; p < 2; p++) {
                int nrow = wn + p * 16 + (l & 7) + ((l >> 4) << 3);
                int ch = kk * 2 + ((l >> 3) & 1);
                uint32_t off = SWZ128((uint32_t)(nrow * 128 + ch * 16));
                uint32_t bh[4], bl[4];
                LDSM4(bh, B0 + 32768 + off);
                LDSM4(bl, B0 + 40960 + off);
#pragma unroll
                for (int s = 0; s < 2; s++) {
                    mma_bf16(acc[s][2*p],     ah[s], bh);
                    mma_bf16(acc[s][2*p],     ah[s], bl);
                    mma_bf16(acc[s][2*p],     al[s], bh);
                    mma_bf16(acc[s][2*p + 1], ah[s], bh + 2);
                    mma_bf16(acc[s][2*p + 1], ah[s], bl + 2);
                    mma_bf16(acc[s][2*p + 1], al[s], bh + 2);
                }
            }
        }
        if (t + 1 < 4) {
            storeb(buf ^ 1);
            __syncthreads();
        }
    }

    float* Cp = g_partA + (size_t)blockIdx.z * (N_ROIS * CEMB);
#pragma unroll
    for (int s = 0; s < 2; s++) {
        int m = wm + s * 16 + (l >> 2);
#pragma unroll
        for (int j = 0; j < 4; j++) {
            int o = n0 + wn + j * 8 + (l & 3) * 2;
            *(float2*)(Cp + (size_t)m * 512 + o) = make_float2(acc[s][j][0], acc[s][j][1]);
            *(float2*)(Cp + (size_t)(m + 8) * 512 + o) = make_float2(acc[s][j][2], acc[s][j][3]);
        }
    }
}

// ---------------------------------------------------------------------------
// HMMA box GEMM: C[128, 12544] = v @ W_box^T, K=512. 196 blocks 128x64.
// ---------------------------------------------------------------------------
__global__ void __launch_bounds__(256)
hmma_box(const float* __restrict__ Wbox)
{
    extern __shared__ __align__(1024) char smem[];
    uint32_t sbase = smem_u32(smem);
    int tid = threadIdx.x, w = tid >> 5, l = tid & 31;
    int n0 = blockIdx.x * 64;
    int kcta = n0 >> 8, o0 = n0 & 255;
    int wm = (w >> 1) * 32, wn = (w & 1) * 32;

    uint4 aR[8];
    float4 bRf[4];
    auto loadg = [&](int t) {
        int k0 = t * 64;
#pragma unroll
        for (int i = 0; i < 4; i++) {
            int s = tid + i * 256, r = s >> 3, c = s & 7;
            size_t eo = (size_t)r * 512 + k0 + c * 8;
            aR[i]     = *(const uint4*)(g_vhi + eo);
            aR[i + 4] = *(const uint4*)(g_vlo + eo);
        }
#pragma unroll
        for (int i = 0; i < 2; i++) {
            int s = tid + i * 256, r = s >> 3, c = s & 7;
            const float* src = Wbox + (size_t)(n0 + r) * 512 + k0 + c * 8;
            bRf[2 * i]     = *(const float4*)src;
            bRf[2 * i + 1] = *(const float4*)(src + 4);
        }
    };
    auto storeb = [&](int buf) {
        char* base = smem + buf * BOXB;
#pragma unroll
        for (int i = 0; i < 4; i++) {
            int s = tid + i * 256, r = s >> 3, c = s & 7;
            uint32_t off = SWZ128((uint32_t)(r * 128 + c * 16));
            *(uint4*)(base + off)         = aR[i];
            *(uint4*)(base + 16384 + off) = aR[i + 4];
        }
#pragma unroll
        for (int i = 0; i < 2; i++) {
            int s = tid + i * 256, r = s >> 3, c = s & 7;
            float fv[8] = {bRf[2*i].x, bRf[2*i].y, bRf[2*i].z, bRf[2*i].w,
                           bRf[2*i+1].x, bRf[2*i+1].y, bRf[2*i+1].z, bRf[2*i+1].w};
            uint4 h4, l4;
            split2(fv[0], fv[1], h4.x, l4.x); split2(fv[2], fv[3], h4.y, l4.y);
            split2(fv[4], fv[5], h4.z, l4.z); split2(fv[6], fv[7], h4.w, l4.w);
            uint32_t off = SWZ128((uint32_t)(r * 128 + c * 16));
            *(uint4*)(base + 32768 + off) = h4;
            *(uint4*)(base + 40960 + off) = l4;
        }
    };

    float acc[2][4][4];
#pragma unroll
    for (int s = 0; s < 2; s++)
#pragma unroll
        for (int j = 0; j < 4; j++)
#pragma unroll
            for (int q = 0; q < 4; q++) acc[s][j][q] = 0.f;

    loadg(0); storeb(0);
    __syncthreads();

    for (int t = 0; t < 8; t++) {
        int buf = t & 1;
        if (t + 1 < 8) loadg(t + 1);
        uint32_t B0 = sbase + buf * BOXB;
#pragma unroll
        for (int kk = 0; kk < 4; kk++) {
            uint32_t ah[2][4], al[2][4];
#pragma unroll
            for (int s = 0; s < 2; s++) {
                int row = wm + s * 16 + (l & 15);
                int ch = kk * 2 + (l >> 4);
                uint32_t off = SWZ128((uint32_t)(row * 128 + ch * 16));
                LDSM4(ah[s], B0 + off);
                LDSM4(al[s], B0 + 16384 + off);
            }
#pragma unroll
            for (int p = 0; p < 2; p++) {
                int nrow = wn + p * 16 + (l & 7) + ((l >> 4) << 3);
                int ch = kk * 2 + ((l >> 3) & 1);
                uint32_t off = SWZ128((uint32_t)(nrow * 128 + ch * 16));
                uint32_t bh[4], bl[4];
                LDSM4(bh, B0 + 32768 + off);
                LDSM4(bl, B0 + 40960 + off);
#pragma unroll
                for (int s = 0; s < 2; s++) {
                    mma_bf16(acc[s][2*p],     ah[s], bh);
                    mma_bf16(acc[s][2*p],     ah[s], bl);
                    mma_bf16(acc[s][2*p],     al[s], bh);
                    mma_bf16(acc[s][2*p + 1], ah[s], bh + 2);
                    mma_bf16(acc[s][2*p + 1], ah[s], bl + 2);
                    mma_bf16(acc[s][2*p + 1], al[s], bh + 2);
                }
            }
        }
        if (t + 1 < 8) {
            storeb(buf ^ 1);
            __syncthreads();
        }
    }

#pragma unroll
    for (int s = 0; s < 2; s++) {
        int m = wm + s * 16 + (l >> 2);
#pragma unroll
        for (int j = 0; j < 4; j++) {
            int o = o0 + wn + j * 8 + (l & 3) * 2;
            uint32_t hi, lo;
            split2(acc[s][j][0], acc[s][j][1], hi, lo);
            size_t b0 = (size_t)(m * 49 + kcta) * 256 + o;
            *(uint32_t*)(g_bhi + b0) = hi;
            *(uint32_t*)(g_blo + b0) = lo;
            split2(acc[s][j][2], acc[s][j][3], hi, lo);
            size_t b1 = (size_t)((m + 8) * 49 + kcta) * 256 + o;
            *(uint32_t*)(g_bhi + b1) = hi;
            *(uint32_t*)(g_blo + b1) = lo;
        }
    }
}

// ---------------------------------------------------------------------------
// HMMA Gxy GEMM: C[6272, 160] = box @ imgxy^T, K=256. 98 blocks 64x160.
// ---------------------------------------------------------------------------
#define GXYB 57344
__global__ void __launch_bounds__(256)
hmma_gxy()
{
    extern __shared__ __align__(1024) char smem[];
    uint32_t sbase = smem_u32(smem);
    int tid = threadIdx.x, w = tid >> 5, l = tid & 31;
    int m0 = blockIdx.x * 64;
    int wm = (w >> 1) * 16, wn = (w & 1) * 80;

    uint4 aR[4], bR[10];
    auto loadg = [&](int t) {
        int k0 = t * 64;
#pragma unroll
        for (int i = 0; i < 2; i++) {
            int s = tid + i * 256, r = s >> 3, c = s & 7;
            size_t eo = (size_t)(m0 + r) * 256 + k0 + c * 8;
            aR[i]     = *(const uint4*)(g_bhi + eo);
            aR[i + 2] = *(const uint4*)(g_blo + eo);
        }
#pragma unroll
        for (int i = 0; i < 5; i++) {
            int s = tid + i * 256, r = s >> 3, c = s & 7;
            size_t eo = (size_t)r * 256 + k0 + c * 8;
            bR[i]     = *(const uint4*)(g_ihi + eo);
            bR[i + 5] = *(const uint4*)(g_ilo + eo);
        }
    };
    auto storeb = [&](int buf) {
        char* base = smem + buf * GXYB;
#pragma unroll
        for (int i = 0; i < 2; i++) {
            int s = tid + i * 256, r = s >> 3, c = s & 7;
            uint32_t off = SWZ128((uint32_t)(r * 128 + c * 16));
            *(uint4*)(base + off)        = aR[i];
            *(uint4*)(base + 8192 + off) = aR[i + 2];
        }
#pragma unroll
        for (int i = 0; i < 5; i++) {
            int s = tid + i * 256, r = s >> 3, c = s & 7;
            uint32_t off = SWZ128((uint32_t)(r * 128 + c * 16));
            *(uint4*)(base + 16384 + off) = bR[i];
            *(uint4*)(base + 36864 + off) = bR[i + 5];
        }
    };

    float acc[10][4];
#pragma unroll
    for (int j = 0; j < 10; j++)
#pragma unroll
        for (int q = 0; q < 4; q++) acc[j][q] = 0.f;

    loadg(0); storeb(0);
    __syncthreads();

    for (int t = 0; t < 4; t++) {
        int buf = t & 1;
        if (t + 1 < 4) loadg(t + 1);
        uint32_t B0 = sbase + buf * GXYB;
#pragma unroll
        for (int kk = 0; kk < 4; kk++) {
            uint32_t ah[4], al[4];
            {
                int row = wm + (l & 15);
                int ch = kk * 2 + (l >> 4);
                uint32_t off = SWZ128((uint32_t)(row * 128 + ch * 16));
                LDSM4(ah, B0 + off);
                LDSM4(al, B0 + 8192 + off);
            }
#pragma unroll
            for (int p = 0; p < 5; p++) {
                int nrow = wn + p * 16 + (l & 7) + ((l >> 4) << 3);
                int ch = kk * 2 + ((l >> 3) & 1);
                uint32_t off = SWZ128((uint32_t)(nrow * 128 + ch * 16));
                uint32_t bh[4], bl[4];
                LDSM4(bh, B0 + 16384 + off);
                LDSM4(bl, B0 + 36864 + off);
                mma_bf16(acc[2*p],     ah, bh);
                mma_bf16(acc[2*p],     ah, bl);
                mma_bf16(acc[2*p],     al, bh);
                mma_bf16(acc[2*p + 1], ah, bh + 2);
                mma_bf16(acc[2*p + 1], ah, bl + 2);
                mma_bf16(acc[2*p + 1], al, bh + 2);
            }
        }
        if (t + 1 < 4) {
            storeb(buf ^ 1);
            __syncthreads();
        }
    }

    int row = m0 + wm + (l >> 2);
#pragma unroll
    for (int j = 0; j < 10; j++) {
        int col = wn + j * 8 + (l & 3) * 2;
        *(float2*)(g_gxy + (size_t)row * 160 + col) =
            make_float2(acc[j][0], acc[j][1]);
        *(float2*)(g_gxy + (size_t)(row + 8) * 160 + col) =
            make_float2(acc[j][2], acc[j][3]);
    }
}

// ---------------------------------------------------------------------------
// geo[nk,h,w] = Gxy[nk,h] + Gxy[nk,64+w]
// ---------------------------------------------------------------------------
__global__ void __launch_bounds__(256)
assemble_kernel(float* __restrict__ outg)
{
    int nk = blockIdx.x;
    __shared__ float sx[HH];
    __shared__ float sy[WW];
    int tid = threadIdx.x;
    if (tid < 160) {
        float vv = g_gxy[nk * 160 + tid];
        if (tid < HH) sx[tid] = vv; else sy[tid - HH] = vv;
    }
    __syncthreads();

    float* base = outg + (size_t)nk * (HH * WW);
#pragma unroll
    for (int t = tid; t < (HH * WW) / 4; t += 256) {
        int h = t / 24;
        int w4 = (t % 24) * 4;
        float gx = sx[h];
        float4 v = make_float4(gx + sy[w4 + 0], gx + sy[w4 + 1],
                               gx + sy[w4 + 2], gx + sy[w4 + 3]);
        *(float4*)(base + h * WW + w4) = v;
    }
}

__global__ void indices_kernel(const float* __restrict__ rois, void* d_out, int mode) {
    int i = threadIdx.x;
    if (i >= N_ROIS) return;
    long long v = (long long)rois[i * 5];
    if (mode == 1)       ((float*)d_out)[i] = (float)v;
    else if (mode == 2)  ((long long*)d_out)[i] = v;
}

// ---------------------------------------------------------------------------
extern "C" void kernel_launch(void* const* d_in, const int* in_sizes, int n_in,
                              void* d_out, int out_size)
{
    const float* rois  = (const float*)d_in[1];
    const float* V_box = (const float*)d_in[2];
    const float* W_box = (const float*)d_in[3];
    const float* W_im  = (const float*)d_in[4];

    float *ex, *ey, *partB;
    cudaGetSymbolAddress((void**)&ex,    g_ex);
    cudaGetSymbolAddress((void**)&ey,    g_ey);
    cudaGetSymbolAddress((void**)&partB, g_partB);

    cudaFuncSetAttribute(hmma_v,   cudaFuncAttributeMaxDynamicSharedMemorySize, 2 * BOXB);
    cudaFuncSetAttribute(hmma_box, cudaFuncAttributeMaxDynamicSharedMemorySize, 2 * BOXB);
    cudaFuncSetAttribute(hmma_gxy, cudaFuncAttributeMaxDynamicSharedMemorySize, 2 * GXYB);

    long long extra = (long long)out_size - GEO_SIZE;
    int mode = (extra == 128) ? 1 : (extra == 256 ? 2 : 0);
    float* outg = (float*)d_out + (extra > 0 ? extra : 0);

    // 1) embeddings (invden table in fp64 once, then fp32 sinf)
    table_kernel<<<2, 256>>>();
    emb_rois_kernel<<<(N_ROIS * 1024 + 255) / 256, 256>>>(rois);
    emb_range_kernel<<<(160 * CEMB + 255) / 256, 256>>>();

    // 2) v = eps @ V_box^T  (HMMA bf16x3, split-K x8 -> 64 blocks)
    hmma_v<<<dim3(8, 1, 8), 256, 2 * BOXB>>>(V_box);
    reduce_v_kernel<<<(N_ROIS * CEMB + 255) / 256, 256>>>();

    // 3) imgx/imgy (SIMT split-K x2) -> imgxy hi/lo [160,256]
    gemm_tpl<32, 64, 32, 2, 4><<<dim3(4, 2, 2), 256>>>(
        ex, CEMB, W_im, 1024, partB, 256, 160 * 256, HH, 256, 512, 256);
    gemm_tpl<32, 64, 32, 2, 4><<<dim3(4, 3, 2), 256>>>(
        ey, CEMB, W_im + 512, 1024, partB + HH * 256, 256, 160 * 256, WW, 256, 512, 256);
    reduce_img_kernel<<<(160 * 256 + 255) / 256, 256>>>();

    // 4) box = v @ W_box^T  (HMMA bf16x3), emits box hi/lo bf16
    hmma_box<<<196, 256, 2 * BOXB>>>(W_box);

    // 5) Gxy = box @ imgxy^T  (HMMA bf16x3)
    hmma_gxy<<<98, 256, 2 * GXYB>>>();

    // 6) indices + broadcast-add assembly
    if (mode) indices_kernel<<<1, 128>>>(rois, d_out, mode);
    assemble_kernel<<<NK, 256>>>(outg);
}

// round 8
// speedup vs baseline: 3.0186x; 1.0159x over previous
#include <cuda_runtime.h>
#include <cuda_bf16.h>
#include <cstdint>

// ---------------------------------------------------------------------------
// GeometricTerm: algebraic collapse + HMMA (mma.sync bf16x3) GEMM chain.
//   geo[nk,h,w] = Gx[nk,h] + Gy[nk,w]
//   v   = eps @ V_box^T            (HMMA bf16x3, split-K x16)
//   box = v @ W_box^T              (HMMA bf16x3, 2 CTAs/SM)
//   Gxy = box @ [imgx;imgy]^T      (HMMA bf16x3, fused assemble epilogue)
// ---------------------------------------------------------------------------

#define N_ROIS 128
#define CEMB   512
#define HH     64
#define WW     96
#define KO     12544
#define NK     6272
#define GEO_SIZE 38535168ll

__device__ __nv_bfloat16 g_ehi[N_ROIS * 2048], g_elo[N_ROIS * 2048];
__device__ float g_ex   [HH * CEMB];
__device__ float g_ey   [WW * CEMB];
__device__ float g_partA[16 * N_ROIS * CEMB];
__device__ float g_partB[2 * 160 * 256];
__device__ __nv_bfloat16 g_vhi[N_ROIS * CEMB], g_vlo[N_ROIS * CEMB];
__device__ __nv_bfloat16 g_ihi[160 * 256],     g_ilo[160 * 256];
__device__ __nv_bfloat16 g_bhi[NK * 256],      g_blo[NK * 256];

// ---------------------------------------------------------------------------
// helpers
// ---------------------------------------------------------------------------
__device__ __forceinline__ uint32_t smem_u32(const void* p) {
    uint32_t a;
    asm("{ .reg .u64 t; cvta.to.shared.u64 t, %1; cvt.u32.u64 %0, t; }"
        : "=r"(a) : "l"(p));
    return a;
}
#define SWZ128(x) ((x) ^ (((x) >> 3) & 0x70))

#define LDSM4(r, a) \
    asm volatile("ldmatrix.sync.aligned.m8n8.x4.shared.b16 {%0,%1,%2,%3}, [%4];" \
        : "=r"((r)[0]), "=r"((r)[1]), "=r"((r)[2]), "=r"((r)[3]) : "r"(a))

__device__ __forceinline__ void mma_bf16(float* d, const uint32_t* a, const uint32_t* b) {
    asm volatile("mma.sync.aligned.m16n8k16.row.col.f32.bf16.bf16.f32 "
        "{%0,%1,%2,%3}, {%4,%5,%6,%7}, {%8,%9}, {%0,%1,%2,%3};"
        : "+f"(d[0]), "+f"(d[1]), "+f"(d[2]), "+f"(d[3])
        : "r"(a[0]), "r"(a[1]), "r"(a[2]), "r"(a[3]), "r"(b[0]), "r"(b[1]));
}

__device__ __forceinline__ void split2(float a, float b, uint32_t& hi, uint32_t& lo) {
    __nv_bfloat16 ha = __float2bfloat16(a), hb = __float2bfloat16(b);
    __nv_bfloat16 la = __float2bfloat16(a - __bfloat162float(ha));
    __nv_bfloat16 lb = __float2bfloat16(b - __bfloat162float(hb));
    hi = (uint32_t)__bfloat16_as_ushort(ha) | ((uint32_t)__bfloat16_as_ushort(hb) << 16);
    lo = (uint32_t)__bfloat16_as_ushort(la) | ((uint32_t)__bfloat16_as_ushort(lb) << 16);
}

// ---------------------------------------------------------------------------
// embeddings: fp32 exp2f + sinf/cosf (invden err ~1e-7 rel, arg <= 64)
// ---------------------------------------------------------------------------
__device__ __forceinline__ float emb_f(float z, int i) {
    const float NEG_L2_1000_OVER_C = -9.965784284662087f / 512.0f;
    float e = (i < 256) ? (float)(2 * i + 1) : (float)(2 * (i - 256));
    float a = z * exp2f(e * NEG_L2_1000_OVER_C);
    return (i < 256) ? sinf(a) : cosf(a);
}

__global__ void emb_rois_kernel(const float* __restrict__ rois) {
    int p = blockIdx.x * blockDim.x + threadIdx.x;
    if (p >= N_ROIS * 1024) return;
    int idx = p * 2;
    int n = idx >> 11, d = idx & 2047;
    int j = d >> 9, i = d & 511;
    float z = rois[n * 5 + 1 + j];
    float v0 = emb_f(z, i), v1 = emb_f(z, i + 1);
    uint32_t hi, lo;
    split2(v0, v1, hi, lo);
    *(uint32_t*)(g_ehi + idx) = hi;
    *(uint32_t*)(g_elo + idx) = lo;
}

__global__ void emb_range_kernel() {
    int idx = blockIdx.x * blockDim.x + threadIdx.x;
    if (idx >= 160 * CEMB) return;
    int r = idx >> 9, i = idx & 511;
    float z = (float)(r < HH ? r : r - HH);
    float val = emb_f(z, i);
    if (r < HH) g_ex[r * CEMB + i] = val;
    else        g_ey[(r - HH) * CEMB + i] = val;
}

// ---------------------------------------------------------------------------
// SIMT split-K SGEMM (img GEMMs only)
// ---------------------------------------------------------------------------
template<int BM, int BN, int BK, int TM, int TN>
__global__ void __launch_bounds__(256)
gemm_tpl(const float* __restrict__ A, int lda,
         const float* __restrict__ B, int ldb,
         float* __restrict__ C, int ldc, long long partStride,
         int M, int N, int K, int kchunk)
{
    constexpr int TX = BN / TN;
    constexpr int TY = BM / TM;
    static_assert(TX * TY == 256, "thread shape");
    constexpr int LA = BM * BK / 1024;
    constexpr int LB = BN * BK / 1024;
    constexpr int KQ = BK / 4;

    __shared__ float As[2][BK][BM];
    __shared__ float Bs[2][BK][BN];

    int tid = threadIdx.x;
    int tx = tid % TX, ty = tid / TX;
    int m0 = blockIdx.y * BM, n0 = blockIdx.x * BN;
    int kstart = blockIdx.z * kchunk;
    int ntiles = (min(K, kstart + kchunk) - kstart) / BK;

    float4 aR[LA], bR[LB];
    auto loadA = [&](int kt) {
#pragma unroll
        for (int i = 0; i < LA; i++) {
            int f = tid + i * 256, r = f / KQ, kq = (f % KQ) * 4;
            int m = m0 + r;
            aR[i] = (m < M) ? *(const float4*)(A + (size_t)m * lda + kstart + kt * BK + kq)
                            : make_float4(0.f, 0.f, 0.f, 0.f);
        }
    };
    auto loadB = [&](int kt) {
#pragma unroll
        for (int i = 0; i < LB; i++) {
            int f = tid + i * 256, r = f / KQ, kq = (f % KQ) * 4;
            int n = n0 + r;
            bR[i] = (n < N) ? *(const float4*)(B + (size_t)n * ldb + kstart + kt * BK + kq)
                            : make_float4(0.f, 0.f, 0.f, 0.f);
        }
    };
    auto storeA = [&](int buf) {
#pragma unroll
        for (int i = 0; i < LA; i++) {
            int f = tid + i * 256, r = f / KQ, kq = (f % KQ) * 4;
            As[buf][kq + 0][r] = aR[i].x; As[buf][kq + 1][r] = aR[i].y;
            As[buf][kq + 2][r] = aR[i].z; As[buf][kq + 3][r] = aR[i].w;
        }
    };
    auto storeB = [&](int buf) {
#pragma unroll
        for (int i = 0; i < LB; i++) {
            int f = tid + i * 256, r = f / KQ, kq = (f % KQ) * 4;
            Bs[buf][kq + 0][r] = bR[i].x; Bs[buf][kq + 1][r] = bR[i].y;
            Bs[buf][kq + 2][r] = bR[i].z; Bs[buf][kq + 3][r] = bR[i].w;
        }
    };

    float acc[TM][TN];
#pragma unroll
    for (int i = 0; i < TM; i++)
#pragma unroll
        for (int j = 0; j < TN; j++) acc[i][j] = 0.f;

    loadA(0); loadB(0); storeA(0); storeB(0);
    __syncthreads();

    int buf = 0;
    for (int t = 0; t < ntiles; t++) {
        if (t + 1 < ntiles) { loadA(t + 1); loadB(t + 1); }
#pragma unroll
        for (int kk = 0; kk < BK; kk++) {
            float a[TM], b[TN];
#pragma unroll
            for (int i = 0; i < TM; i += 2) {
                float2 v2 = *(const float2*)&As[buf][kk][ty * TM + i];
                a[i] = v2.x; a[i + 1] = v2.y;
            }
#pragma unroll
            for (int j = 0; j < TN; j += 4) {
                float4 v4 = *(const float4*)&Bs[buf][kk][tx * TN + j];
                b[j] = v4.x; b[j + 1] = v4.y; b[j + 2] = v4.z; b[j + 3] = v4.w;
            }
#pragma unroll
            for (int i = 0; i < TM; i++)
#pragma unroll
                for (int j = 0; j < TN; j++) acc[i][j] += a[i] * b[j];
        }
        if (t + 1 < ntiles) {
            storeA(buf ^ 1); storeB(buf ^ 1);
            __syncthreads();
            buf ^= 1;
        }
    }

    float* Cb = C + (long long)blockIdx.z * partStride;
#pragma unroll
    for (int i = 0; i < TM; i++) {
        int m = m0 + ty * TM + i;
        if (m >= M) continue;
#pragma unroll
        for (int j = 0; j < TN; j++) {
            int n = n0 + tx * TN + j;
            if (n < N) Cb[(size_t)m * ldc + n] = acc[i][j];
        }
    }
}

// reductions emitting bf16 hi/lo
__global__ void reduce_v_kernel() {
    int i = blockIdx.x * blockDim.x + threadIdx.x;
    if (i >= N_ROIS * CEMB) return;
    float s = 0.f;
#pragma unroll
    for (int p = 0; p < 16; p++) s += g_partA[p * (N_ROIS * CEMB) + i];
    __nv_bfloat16 h = __float2bfloat16(s);
    g_vhi[i] = h;
    g_vlo[i] = __float2bfloat16(s - __bfloat162float(h));
}
__global__ void reduce_img_kernel() {
    int i = blockIdx.x * blockDim.x + threadIdx.x;
    if (i >= 160 * 256) return;
    float s = g_partB[i] + g_partB[160 * 256 + i];
    __nv_bfloat16 h = __float2bfloat16(s);
    g_ihi[i] = h;
    g_ilo[i] = __float2bfloat16(s - __bfloat162float(h));
}

// ---------------------------------------------------------------------------
// HMMA v GEMM: C[128,512] = eps @ V_box^T, K=2048, split-K x16 -> 128 blocks.
// tile 128M x 64N; kchunk=128 (2 BK iters). fp32 partials.
// buf (49152B): Ahi 16K | Alo 16K | Bhi 8K | Blo 8K.
// ---------------------------------------------------------------------------
#define BOXB 49152
__global__ void __launch_bounds__(256)
hmma_v(const float* __restrict__ Vbox)
{
    extern __shared__ __align__(1024) char smem[];
    uint32_t sbase = smem_u32(smem);
    int tid = threadIdx.x, w = tid >> 5, l = tid & 31;
    int n0 = blockIdx.x * 64;
    int kstart = blockIdx.z * 128;
    int wm = (w >> 1) * 32, wn = (w & 1) * 32;

    uint4 aR[8];
    float4 bRf[4];
    auto loadg = [&](int t) {
        int k0 = kstart + t * 64;
#pragma unroll
        for (int i = 0; i < 4; i++) {
            int s = tid + i * 256, r = s >> 3, c = s & 7;
            size_t eo = (size_t)r * 2048 + k0 + c * 8;
            aR[i]     = *(const uint4*)(g_ehi + eo);
            aR[i + 4] = *(const uint4*)(g_elo + eo);
        }
#pragma unroll
        for (int i = 0; i < 2; i++) {
            int s = tid + i * 256, r = s >> 3, c = s & 7;
            const float* src = Vbox + (size_t)(n0 + r) * 2048 + k0 + c * 8;
            bRf[2 * i]     = *(const float4*)src;
            bRf[2 * i + 1] = *(const float4*)(src + 4);
        }
    };
    auto storeb = [&](int buf) {
        char* base = smem + buf * BOXB;
#pragma unroll
        for (int i = 0; i < 4; i++) {
            int s = tid + i * 256, r = s >> 3, c = s & 7;
            uint32_t off = SWZ128((uint32_t)(r * 128 + c * 16));
            *(uint4*)(base + off)         = aR[i];
            *(uint4*)(base + 16384 + off) = aR[i + 4];
        }
#pragma unroll
        for (int i = 0; i < 2; i++) {
            int s = tid + i * 256, r = s >> 3, c = s & 7;
            float fv[8] = {bRf[2*i].x, bRf[2*i].y, bRf[2*i].z, bRf[2*i].w,
                           bRf[2*i+1].x, bRf[2*i+1].y, bRf[2*i+1].z, bRf[2*i+1].w};
            uint4 h4, l4;
            split2(fv[0], fv[1], h4.x, l4.x); split2(fv[2], fv[3], h4.y, l4.y);
            split2(fv[4], fv[5], h4.z, l4.z); split2(fv[6], fv[7], h4.w, l4.w);
            uint32_t off = SWZ128((uint32_t)(r * 128 + c * 16));
            *(uint4*)(base + 32768 + off) = h4;
            *(uint4*)(base + 40960 + off) = l4;
        }
    };

    float acc[2][4][4];
#pragma unroll
    for (int s = 0; s < 2; s++)
#pragma unroll
        for (int j = 0; j < 4; j++)
#pragma unroll
            for (int q = 0; q < 4; q++) acc[s][j][q] = 0.f;

    loadg(0); storeb(0);
    __syncthreads();

    for (int t = 0; t < 2; t++) {
        int buf = t & 1;
        if (t + 1 < 2) loadg(t + 1);
        uint32_t B0 = sbase + buf * BOXB;
#pragma unroll
        for (int kk = 0; kk < 4; kk++) {
            uint32_t ah[2][4], al[2][4];
#pragma unroll
            for (int s = 0; s < 2; s++) {
                int row = wm + s * 16 + (l & 15);
                int ch = kk * 2 + (l >> 4);
                uint32_t off = SWZ128((uint32_t)(row * 128 + ch * 16));
                LDSM4(ah[s], B0 + off);
                LDSM4(al[s], B0 + 16384 + off);
            }
#pragma unroll
            for (int p = 0; p < 2; p++) {
                int nrow = wn + p * 16 + (l & 7) + ((l >> 4) << 3);
                int ch = kk * 2 + ((l >> 3) & 1);
                uint32_t off = SWZ128((uint32_t)(nrow * 128 + ch * 16));
                uint32_t bh[4], bl[4];
                LDSM4(bh, B0 + 32768 + off);
                LDSM4(bl, B0 + 40960 + off);
#pragma unroll
                for (int s = 0; s < 2; s++) {
                    mma_bf16(acc[s][2*p],     ah[s], bh);
                    mma_bf16(acc[s][2*p],     ah[s], bl);
                    mma_bf16(acc[s][2*p],     al[s], bh);
                    mma_bf16(acc[s][2*p + 1], ah[s], bh + 2);
                    mma_bf16(acc[s][2*p + 1], ah[s], bl + 2);
                    mma_bf16(acc[s][2*p + 1], al[s], bh + 2);
                }
            }
        }
        if (t + 1 < 2) {
            storeb(buf ^ 1);
            __syncthreads();
        }
    }

    float* Cp = g_partA + (size_t)blockIdx.z * (N_ROIS * CEMB);
#pragma unroll
    for (int s = 0; s < 2; s++) {
        int m = wm + s * 16 + (l >> 2);
#pragma unroll
        for (int j = 0; j < 4; j++) {
            int o = n0 + wn + j * 8 + (l & 3) * 2;
            *(float2*)(Cp + (size_t)m * 512 + o) = make_float2(acc[s][j][0], acc[s][j][1]);
            *(float2*)(Cp + (size_t)(m + 8) * 512 + o) = make_float2(acc[s][j][2], acc[s][j][3]);
        }
    }
}

// ---------------------------------------------------------------------------
// HMMA box GEMM: C[128, 12544] = v @ W_box^T, K=512. 196 blocks 128x64.
// 2 CTAs/SM (regs<=128, 2x96K smem).
// ---------------------------------------------------------------------------
__global__ void __launch_bounds__(256, 2)
hmma_box(const float* __restrict__ Wbox)
{
    extern __shared__ __align__(1024) char smem[];
    uint32_t sbase = smem_u32(smem);
    int tid = threadIdx.x, w = tid >> 5, l = tid & 31;
    int n0 = blockIdx.x * 64;
    int kcta = n0 >> 8, o0 = n0 & 255;
    int wm = (w >> 1) * 32, wn = (w & 1) * 32;

    uint4 aR[8];
    float4 bRf[4];
    auto loadg = [&](int t) {
        int k0 = t * 64;
#pragma unroll
        for (int i = 0; i < 4; i++) {
            int s = tid + i * 256, r = s >> 3, c = s & 7;
            size_t eo = (size_t)r * 512 + k0 + c * 8;
            aR[i]     = *(const uint4*)(g_vhi + eo);
            aR[i + 4] = *(const uint4*)(g_vlo + eo);
        }
#pragma unroll
        for (int i = 0; i < 2; i++) {
            int s = tid + i * 256, r = s >> 3, c = s & 7;
            const float* src = Wbox + (size_t)(n0 + r) * 512 + k0 + c * 8;
            bRf[2 * i]     = *(const float4*)src;
            bRf[2 * i + 1] = *(const float4*)(src + 4);
        }
    };
    auto storeb = [&](int buf) {
        char* base = smem + buf * BOXB;
#pragma unroll
        for (int i = 0; i < 4; i++) {
            int s = tid + i * 256, r = s >> 3, c = s & 7;
            uint32_t off = SWZ128((uint32_t)(r * 128 + c * 16));
            *(uint4*)(base + off)         = aR[i];
            *(uint4*)(base + 16384 + off) = aR[i + 4];
        }
#pragma unroll
        for (int i = 0; i < 2; i++) {
            int s = tid + i * 256, r = s >> 3, c = s & 7;
            float fv[8] = {bRf[2*i].x, bRf[2*i].y, bRf[2*i].z, bRf[2*i].w,
                           bRf[2*i+1].x, bRf[2*i+1].y, bRf[2*i+1].z, bRf[2*i+1].w};
            uint4 h4, l4;
            split2(fv[0], fv[1], h4.x, l4.x); split2(fv[2], fv[3], h4.y, l4.y);
            split2(fv[4], fv[5], h4.z, l4.z); split2(fv[6], fv[7], h4.w, l4.w);
            uint32_t off = SWZ128((uint32_t)(r * 128 + c * 16));
            *(uint4*)(base + 32768 + off) = h4;
            *(uint4*)(base + 40960 + off) = l4;
        }
    };

    float acc[2][4][4];
#pragma unroll
    for (int s = 0; s < 2; s++)
#pragma unroll
        for (int j = 0; j < 4; j++)
#pragma unroll
            for (int q = 0; q < 4; q++) acc[s][j][q] = 0.f;

    loadg(0); storeb(0);
    __syncthreads();

    for (int t = 0; t < 8; t++) {
        int buf = t & 1;
        if (t + 1 < 8) loadg(t + 1);
        uint32_t B0 = sbase + buf * BOXB;
#pragma unroll
        for (int kk = 0; kk < 4; kk++) {
            uint32_t ah[2][4], al[2][4];
#pragma unroll
            for (int s = 0; s < 2; s++) {
                int row = wm + s * 16 + (l & 15);
                int ch = kk * 2 + (l >> 4);
                uint32_t off = SWZ128((uint32_t)(row * 128 + ch * 16));
                LDSM4(ah[s], B0 + off);
                LDSM4(al[s], B0 + 16384 + off);
            }
#pragma unroll
            for (int p = 0; p < 2; p++) {
                int nrow = wn + p * 16 + (l & 7) + ((l >> 4) << 3);
                int ch = kk * 2 + ((l >> 3) & 1);
                uint32_t off = SWZ128((uint32_t)(nrow * 128 + ch * 16));
                uint32_t bh[4], bl[4];
                LDSM4(bh, B0 + 32768 + off);
                LDSM4(bl, B0 + 40960 + off);
#pragma unroll
                for (int s = 0; s < 2; s++) {
                    mma_bf16(acc[s][2*p],     ah[s], bh);
                    mma_bf16(acc[s][2*p],     ah[s], bl);
                    mma_bf16(acc[s][2*p],     al[s], bh);
                    mma_bf16(acc[s][2*p + 1], ah[s], bh + 2);
                    mma_bf16(acc[s][2*p + 1], ah[s], bl + 2);
                    mma_bf16(acc[s][2*p + 1], al[s], bh + 2);
                }
            }
        }
        if (t + 1 < 8) {
            storeb(buf ^ 1);
            __syncthreads();
        }
    }

#pragma unroll
    for (int s = 0; s < 2; s++) {
        int m = wm + s * 16 + (l >> 2);
#pragma unroll
        for (int j = 0; j < 4; j++) {
            int o = o0 + wn + j * 8 + (l & 3) * 2;
            uint32_t hi, lo;
            split2(acc[s][j][0], acc[s][j][1], hi, lo);
            size_t b0 = (size_t)(m * 49 + kcta) * 256 + o;
            *(uint32_t*)(g_bhi + b0) = hi;
            *(uint32_t*)(g_blo + b0) = lo;
            split2(acc[s][j][2], acc[s][j][3], hi, lo);
            size_t b1 = (size_t)((m + 8) * 49 + kcta) * 256 + o;
            *(uint32_t*)(g_bhi + b1) = hi;
            *(uint32_t*)(g_blo + b1) = lo;
        }
    }
}

// ---------------------------------------------------------------------------
// HMMA Gxy GEMM + fused assemble: 98 blocks 64x160, K=256.
// After MMA, acc -> smem sxy[64][160]; block writes its 64 geo rows directly:
//   geo[nk,h,w] = sxy[nk][h] + sxy[nk][64+w]
// ---------------------------------------------------------------------------
#define GXYB 57344
__global__ void __launch_bounds__(256)
hmma_gxy(float* __restrict__ outg)
{
    extern __shared__ __align__(1024) char smem[];
    uint32_t sbase = smem_u32(smem);
    int tid = threadIdx.x, w = tid >> 5, l = tid & 31;
    int m0 = blockIdx.x * 64;
    int wm = (w >> 1) * 16, wn = (w & 1) * 80;

    uint4 aR[4], bR[10];
    auto loadg = [&](int t) {
        int k0 = t * 64;
#pragma unroll
        for (int i = 0; i < 2; i++) {
            int s = tid + i * 256, r = s >> 3, c = s & 7;
            size_t eo = (size_t)(m0 + r) * 256 + k0 + c * 8;
            aR[i]     = *(const uint4*)(g_bhi + eo);
            aR[i + 2] = *(const uint4*)(g_blo + eo);
        }
#pragma unroll
        for (int i = 0; i < 5; i++) {
            int s = tid + i * 256, r = s >> 3, c = s & 7;
            size_t eo = (size_t)r * 256 + k0 + c * 8;
            bR[i]     = *(const uint4*)(g_ihi + eo);
            bR[i + 5] = *(const uint4*)(g_ilo + eo);
        }
    };
    auto storeb = [&](int buf) {
        char* base = smem + buf * GXYB;
#pragma unroll
        for (int i = 0; i < 2; i++) {
            int s = tid + i * 256, r = s >> 3, c = s & 7;
            uint32_t off = SWZ128((uint32_t)(r * 128 + c * 16));
            *(uint4*)(base + off)        = aR[i];
            *(uint4*)(base + 8192 + off) = aR[i + 2];
        }
#pragma unroll
        for (int i = 0; i < 5; i++) {
            int s = tid + i * 256, r = s >> 3, c = s & 7;
            uint32_t off = SWZ128((uint32_t)(r * 128 + c * 16));
            *(uint4*)(base + 16384 + off) = bR[i];
            *(uint4*)(base + 36864 + off) = bR[i + 5];
        }
    };

    float acc[10][4];
#pragma unroll
    for (int j = 0; j < 10; j++)
#pragma unroll
        for (int q = 0; q < 4; q++) acc[j][q] = 0.f;

    loadg(0); storeb(0);
    __syncthreads();

    for (int t = 0; t < 4; t++) {
        int buf = t & 1;
        if (t + 1 < 4) loadg(t + 1);
        uint32_t B0 = sbase + buf * GXYB;
#pragma unroll
        for (int kk = 0; kk < 4; kk++) {
            uint32_t ah[4], al[4];
            {
                int row = wm + (l & 15);
                int ch = kk * 2 + (l >> 4);
                uint32_t off = SWZ128((uint32_t)(row * 128 + ch * 16));
                LDSM4(ah, B0 + off);
                LDSM4(al, B0 + 8192 + off);
            }
#pragma unroll
            for (int p = 0; p < 5; p++) {
                int nrow = wn + p * 16 + (l & 7) + ((l >> 4) << 3);
                int ch = kk * 2 + ((l >> 3) & 1);
                uint32_t off = SWZ128((uint32_t)(nrow * 128 + ch * 16));
                uint32_t bh[4], bl[4];
                LDSM4(bh, B0 + 16384 + off);
                LDSM4(bl, B0 + 36864 + off);
                mma_bf16(acc[2*p],     ah, bh);
                mma_bf16(acc[2*p],     ah, bl);
                mma_bf16(acc[2*p],     al, bh);
                mma_bf16(acc[2*p + 1], ah, bh + 2);
                mma_bf16(acc[2*p + 1], ah, bl + 2);
                mma_bf16(acc[2*p + 1], al, bh + 2);
            }
        }
        if (t + 1 < 4) {
            storeb(buf ^ 1);
            __syncthreads();
        }
    }

    // fused assemble: acc -> smem sxy[64][160], then broadcast-add write
    __syncthreads();                       // all warps done with smem buffers
    float* sxy = (float*)smem;
    {
        int row = wm + (l >> 2);
#pragma unroll
        for (int j = 0; j < 10; j++) {
            int col = wn + j * 8 + (l & 3) * 2;
            sxy[row * 160 + col]           = acc[j][0];
            sxy[row * 160 + col + 1]       = acc[j][1];
            sxy[(row + 8) * 160 + col]     = acc[j][2];
            sxy[(row + 8) * 160 + col + 1] = acc[j][3];
        }
    }
    __syncthreads();

    // 64 rows x 1536 float4 per block
    for (int idx = tid; idx < 64 * 1536; idx += 256) {
        int nkl = idx / 1536, rem = idx - nkl * 1536;
        int h = rem / 24, w4 = (rem - h * 24) * 4;
        const float* rowp = sxy + nkl * 160;
        float gx = rowp[h];
        float4 v = make_float4(gx + rowp[64 + w4 + 0], gx + rowp[64 + w4 + 1],
                               gx + rowp[64 + w4 + 2], gx + rowp[64 + w4 + 3]);
        *(float4*)(outg + (size_t)(m0 + nkl) * 6144 + h * 96 + w4) = v;
    }
}

__global__ void indices_kernel(const float* __restrict__ rois, void* d_out, int mode) {
    int i = threadIdx.x;
    if (i >= N_ROIS) return;
    long long v = (long long)rois[i * 5];
    if (mode == 1)       ((float*)d_out)[i] = (float)v;
    else if (mode == 2)  ((long long*)d_out)[i] = v;
}

// ---------------------------------------------------------------------------
extern "C" void kernel_launch(void* const* d_in, const int* in_sizes, int n_in,
                              void* d_out, int out_size)
{
    const float* rois  = (const float*)d_in[1];
    const float* V_box = (const float*)d_in[2];
    const float* W_box = (const float*)d_in[3];
    const float* W_im  = (const float*)d_in[4];

    float *ex, *ey, *partB;
    cudaGetSymbolAddress((void**)&ex,    g_ex);
    cudaGetSymbolAddress((void**)&ey,    g_ey);
    cudaGetSymbolAddress((void**)&partB, g_partB);

    cudaFuncSetAttribute(hmma_v,   cudaFuncAttributeMaxDynamicSharedMemorySize, 2 * BOXB);
    cudaFuncSetAttribute(hmma_box, cudaFuncAttributeMaxDynamicSharedMemorySize, 2 * BOXB);
    cudaFuncSetAttribute(hmma_gxy, cudaFuncAttributeMaxDynamicSharedMemorySize, 2 * GXYB);

    long long extra = (long long)out_size - GEO_SIZE;
    int mode = (extra == 128) ? 1 : (extra == 256 ? 2 : 0);
    float* outg = (float*)d_out + (extra > 0 ? extra : 0);

    // 1) embeddings
    emb_rois_kernel<<<(N_ROIS * 1024 + 255) / 256, 256>>>(rois);
    emb_range_kernel<<<(160 * CEMB + 255) / 256, 256>>>();

    // 2) v = eps @ V_box^T  (HMMA bf16x3, split-K x16 -> 128 blocks)
    hmma_v<<<dim3(8, 1, 16), 256, 2 * BOXB>>>(V_box);
    reduce_v_kernel<<<(N_ROIS * CEMB + 255) / 256, 256>>>();

    // 3) imgx/imgy (SIMT split-K x2) -> imgxy hi/lo [160,256]
    gemm_tpl<32, 64, 32, 2, 4><<<dim3(4, 2, 2), 256>>>(
        ex, CEMB, W_im, 1024, partB, 256, 160 * 256, HH, 256, 512, 256);
    gemm_tpl<32, 64, 32, 2, 4><<<dim3(4, 3, 2), 256>>>(
        ey, CEMB, W_im + 512, 1024, partB + HH * 256, 256, 160 * 256, WW, 256, 512, 256);
    reduce_img_kernel<<<(160 * 256 + 255) / 256, 256>>>();

    // 4) box = v @ W_box^T  (HMMA bf16x3, 2 CTAs/SM), emits box hi/lo bf16
    hmma_box<<<196, 256, 2 * BOXB>>>(W_box);

    // 5) Gxy + fused assemble -> geo
    if (mode) indices_kernel<<<1, 128>>>(rois, d_out, mode);
    hmma_gxy<<<98, 256, 2 * GXYB>>>(outg);
}

// round 9
// speedup vs baseline: 3.6632x; 1.2136x over previous
#include <cuda_runtime.h>
#include <cuda_bf16.h>
#include <cstdint>

// ---------------------------------------------------------------------------
// GeometricTerm: algebraic collapse + HMMA (mma.sync bf16x3) GEMM chain.
//   geo[nk,h,w] = Gx[nk,h] + Gy[nk,w]
// 5 launches: emb_all -> {hmma_v | img} -> reduce_v -> hmma_box -> gxy+assemble
// ---------------------------------------------------------------------------

#define N_ROIS 128
#define CEMB   512
#define HH     64
#define WW     96
#define KO     12544
#define NK     6272
#define GEO_SIZE 38535168ll

__device__ __nv_bfloat16 g_ehi[N_ROIS * 2048], g_elo[N_ROIS * 2048];
__device__ float g_ex   [HH * CEMB];
__device__ float g_ey   [WW * CEMB];
__device__ float g_partA[16 * N_ROIS * CEMB];
__device__ __nv_bfloat16 g_vhi[N_ROIS * CEMB], g_vlo[N_ROIS * CEMB];
__device__ __nv_bfloat16 g_ihi[160 * 256],     g_ilo[160 * 256];
__device__ __nv_bfloat16 g_bhi[NK * 256],      g_blo[NK * 256];

// ---------------------------------------------------------------------------
// helpers
// ---------------------------------------------------------------------------
__device__ __forceinline__ uint32_t smem_u32(const void* p) {
    uint32_t a;
    asm("{ .reg .u64 t; cvta.to.shared.u64 t, %1; cvt.u32.u64 %0, t; }"
        : "=r"(a) : "l"(p));
    return a;
}
#define SWZ128(x) ((x) ^ (((x) >> 3) & 0x70))

#define LDSM4(r, a) \
    asm volatile("ldmatrix.sync.aligned.m8n8.x4.shared.b16 {%0,%1,%2,%3}, [%4];" \
        : "=r"((r)[0]), "=r"((r)[1]), "=r"((r)[2]), "=r"((r)[3]) : "r"(a))

__device__ __forceinline__ void mma_bf16(float* d, const uint32_t* a, const uint32_t* b) {
    asm volatile("mma.sync.aligned.m16n8k16.row.col.f32.bf16.bf16.f32 "
        "{%0,%1,%2,%3}, {%4,%5,%6,%7}, {%8,%9}, {%0,%1,%2,%3};"
        : "+f"(d[0]), "+f"(d[1]), "+f"(d[2]), "+f"(d[3])
        : "r"(a[0]), "r"(a[1]), "r"(a[2]), "r"(a[3]), "r"(b[0]), "r"(b[1]));
}

__device__ __forceinline__ void split2(float a, float b, uint32_t& hi, uint32_t& lo) {
    __nv_bfloat16 ha = __float2bfloat16(a), hb = __float2bfloat16(b);
    __nv_bfloat16 la = __float2bfloat16(a - __bfloat162float(ha));
    __nv_bfloat16 lb = __float2bfloat16(b - __bfloat162float(hb));
    hi = (uint32_t)__bfloat16_as_ushort(ha) | ((uint32_t)__bfloat16_as_ushort(hb) << 16);
    lo = (uint32_t)__bfloat16_as_ushort(la) | ((uint32_t)__bfloat16_as_ushort(lb) << 16);
}

// ---------------------------------------------------------------------------
// embeddings (fp32 exp2f + sinf/cosf)
// ---------------------------------------------------------------------------
__device__ __forceinline__ float emb_f(float z, int i) {
    const float NEG_L2_1000_OVER_C = -9.965784284662087f / 512.0f;
    float e = (i < 256) ? (float)(2 * i + 1) : (float)(2 * (i - 256));
    float a = z * exp2f(e * NEG_L2_1000_OVER_C);
    return (i < 256) ? sinf(a) : cosf(a);
}

// blocks 0..511: rois eps -> bf16 hi/lo; blocks 512..831: ex/ey fp32
__global__ void emb_all_kernel(const float* __restrict__ rois) {
    int bid = blockIdx.x, tid = threadIdx.x;
    if (bid < 512) {
        int p = bid * 256 + tid;          // 0..131071 (pairs)
        int idx = p * 2;
        int n = idx >> 11, d = idx & 2047;
        int j = d >> 9, i = d & 511;
        float z = rois[n * 5 + 1 + j];
        float v0 = emb_f(z, i), v1 = emb_f(z, i + 1);
        uint32_t hi, lo;
        split2(v0, v1, hi, lo);
        *(uint32_t*)(g_ehi + idx) = hi;
        *(uint32_t*)(g_elo + idx) = lo;
    } else {
        int idx = (bid - 512) * 256 + tid;   // 0..81919
        int r = idx >> 9, i = idx & 511;
        float z = (float)(r < HH ? r : r - HH);
        float val = emb_f(z, i);
        if (r < HH) g_ex[r * CEMB + i] = val;
        else        g_ey[(r - HH) * CEMB + i] = val;
    }
}

// ---------------------------------------------------------------------------
// Fused launch: blocks 0..127 = hmma_v (split-K x16); blocks 128..147 = img
// SIMT GEMM (32x64 tiles, K=512) emitting imgxy bf16 hi/lo directly.
// dynamic smem: 96KB (v uses both 48K bufs; img uses first 24KB).
// ---------------------------------------------------------------------------
#define BOXB 49152
__global__ void __launch_bounds__(256)
hmma_v_img(const float* __restrict__ Vbox, const float* __restrict__ Wim)
{
    extern __shared__ __align__(1024) char smem[];
    int tid = threadIdx.x;

    if (blockIdx.x < 128) {
        // ----------------- v = eps @ V_box^T, HMMA bf16x3, split-K -----------
        uint32_t sbase = smem_u32(smem);
        int w = tid >> 5, l = tid & 31;
        int n0 = (blockIdx.x & 7) * 64;
        int kstart = (blockIdx.x >> 3) * 128;
        int wm = (w >> 1) * 32, wn = (w & 1) * 32;

        uint4 aR[8];
        float4 bRf[4];
        auto loadg = [&](int t) {
            int k0 = kstart + t * 64;
#pragma unroll
            for (int i = 0; i < 4; i++) {
                int s = tid + i * 256, r = s >> 3, c = s & 7;
                size_t eo = (size_t)r * 2048 + k0 + c * 8;
                aR[i]     = *(const uint4*)(g_ehi + eo);
                aR[i + 4] = *(const uint4*)(g_elo + eo);
            }
#pragma unroll
            for (int i = 0; i < 2; i++) {
                int s = tid + i * 256, r = s >> 3, c = s & 7;
                const float* src = Vbox + (size_t)(n0 + r) * 2048 + k0 + c * 8;
                bRf[2 * i]     = *(const float4*)src;
                bRf[2 * i + 1] = *(const float4*)(src + 4);
            }
        };
        auto storeb = [&](int buf) {
            char* base = smem + buf * BOXB;
#pragma unroll
            for (int i = 0; i < 4; i++) {
                int s = tid + i * 256, r = s >> 3, c = s & 7;
                uint32_t off = SWZ128((uint32_t)(r * 128 + c * 16));
                *(uint4*)(base + off)         = aR[i];
                *(uint4*)(base + 16384 + off) = aR[i + 4];
            }
#pragma unroll
            for (int i = 0; i < 2; i++) {
                int s = tid + i * 256, r = s >> 3, c = s & 7;
                float fv[8] = {bRf[2*i].x, bRf[2*i].y, bRf[2*i].z, bRf[2*i].w,
                               bRf[2*i+1].x, bRf[2*i+1].y, bRf[2*i+1].z, bRf[2*i+1].w};
                uint4 h4, l4;
                split2(fv[0], fv[1], h4.x, l4.x); split2(fv[2], fv[3], h4.y, l4.y);
                split2(fv[4], fv[5], h4.z, l4.z); split2(fv[6], fv[7], h4.w, l4.w);
                uint32_t off = SWZ128((uint32_t)(r * 128 + c * 16));
                *(uint4*)(base + 32768 + off) = h4;
                *(uint4*)(base + 40960 + off) = l4;
            }
        };

        float acc[2][4][4];
#pragma unroll
        for (int s = 0; s < 2; s++)
#pragma unroll
            for (int j = 0; j < 4; j++)
#pragma unroll
                for (int q = 0; q < 4; q++) acc[s][j][q] = 0.f;

        loadg(0); storeb(0);
        __syncthreads();

        for (int t = 0; t < 2; t++) {
            int buf = t & 1;
            if (t + 1 < 2) loadg(t + 1);
            uint32_t B0 = sbase + buf * BOXB;
#pragma unroll
            for (int kk = 0; kk < 4; kk++) {
                uint32_t ah[2][4], al[2][4];
#pragma unroll
                for (int s = 0; s < 2; s++) {
                    int row = wm + s * 16 + (l & 15);
                    int ch = kk * 2 + (l >> 4);
                    uint32_t off = SWZ128((uint32_t)(row * 128 + ch * 16));
                    LDSM4(ah[s], B0 + off);
                    LDSM4(al[s], B0 + 16384 + off);
                }
#pragma unroll
                for (int p = 0; p < 2; p++) {
                    int nrow = wn + p * 16 + (l & 7) + ((l >> 4) << 3);
                    int ch = kk * 2 + ((l >> 3) & 1);
                    uint32_t off = SWZ128((uint32_t)(nrow * 128 + ch * 16));
                    uint32_t bh[4], bl[4];
                    LDSM4(bh, B0 + 32768 + off);
                    LDSM4(bl, B0 + 40960 + off);
#pragma unroll
                    for (int s = 0; s < 2; s++) {
                        mma_bf16(acc[s][2*p],     ah[s], bh);
                        mma_bf16(acc[s][2*p],     ah[s], bl);
                        mma_bf16(acc[s][2*p],     al[s], bh);
                        mma_bf16(acc[s][2*p + 1], ah[s], bh + 2);
                        mma_bf16(acc[s][2*p + 1], ah[s], bl + 2);
                        mma_bf16(acc[s][2*p + 1], al[s], bh + 2);
                    }
                }
            }
            if (t + 1 < 2) {
                storeb(buf ^ 1);
                __syncthreads();
            }
        }

        float* Cp = g_partA + (size_t)(blockIdx.x >> 3) * (N_ROIS * CEMB);
#pragma unroll
        for (int s = 0; s < 2; s++) {
            int m = wm + s * 16 + (l >> 2);
#pragma unroll
            for (int j = 0; j < 4; j++) {
                int o = n0 + wn + j * 8 + (l & 3) * 2;
                *(float2*)(Cp + (size_t)m * 512 + o) = make_float2(acc[s][j][0], acc[s][j][1]);
                *(float2*)(Cp + (size_t)(m + 8) * 512 + o) = make_float2(acc[s][j][2], acc[s][j][3]);
            }
        }
    } else {
        // ----------------- img: [160,256] = [ex;ey] @ W_im halves^T ----------
        // SIMT 32x64 tile, K=512, double-buffered. 20 blocks.
        float* As = (float*)smem;               // [2][32][32]
        float* Bs = (float*)(smem + 8192);      // [2][32][64]
        int b = blockIdx.x - 128;
        int m0 = (b % 5) * 32;                  // row in [0,160)
        int n0 = (b / 5) * 64;
        const float* Abase = (m0 < HH) ? g_ex + (size_t)m0 * CEMB
                                       : g_ey + (size_t)(m0 - HH) * CEMB;
        int boff = (m0 < HH) ? 0 : 512;
        int tx = tid & 15, ty = tid >> 4;

        float4 aR;
        float4 bR[2];
        auto loadA = [&](int t) {
            int r = tid >> 3, kq = (tid & 7) * 4;
            aR = *(const float4*)(Abase + (size_t)r * CEMB + t * 32 + kq);
        };
        auto loadB = [&](int t) {
#pragma unroll
            for (int i = 0; i < 2; i++) {
                int f = tid + i * 256, r = f >> 3, kq = (f & 7) * 4;
                bR[i] = *(const float4*)(Wim + (size_t)(n0 + r) * 1024 + boff + t * 32 + kq);
            }
        };
        auto storeAB = [&](int buf) {
            int r = tid >> 3, kq = (tid & 7) * 4;
            As[buf * 1024 + (kq + 0) * 32 + r] = aR.x;
            As[buf * 1024 + (kq + 1) * 32 + r] = aR.y;
            As[buf * 1024 + (kq + 2) * 32 + r] = aR.z;
            As[buf * 1024 + (kq + 3) * 32 + r] = aR.w;
#pragma unroll
            for (int i = 0; i < 2; i++) {
                int f = tid + i * 256, rr = f >> 3, kq2 = (f & 7) * 4;
                Bs[buf * 2048 + (kq2 + 0) * 64 + rr] = bR[i].x;
                Bs[buf * 2048 + (kq2 + 1) * 64 + rr] = bR[i].y;
                Bs[buf * 2048 + (kq2 + 2) * 64 + rr] = bR[i].z;
                Bs[buf * 2048 + (kq2 + 3) * 64 + rr] = bR[i].w;
            }
        };

        float acc[2][4];
#pragma unroll
        for (int i = 0; i < 2; i++)
#pragma unroll
            for (int j = 0; j < 4; j++) acc[i][j] = 0.f;

        loadA(0); loadB(0); storeAB(0);
        __syncthreads();

        for (int t = 0; t < 16; t++) {
            int buf = t & 1;
            if (t + 1 < 16) { loadA(t + 1); loadB(t + 1); }
#pragma unroll
            for (int kk = 0; kk < 32; kk++) {
                float2 a2 = *(const float2*)&As[buf * 1024 + kk * 32 + ty * 2];
                float4 b4 = *(const float4*)&Bs[buf * 2048 + kk * 64 + tx * 4];
                acc[0][0] += a2.x * b4.x; acc[0][1] += a2.x * b4.y;
                acc[0][2] += a2.x * b4.z; acc[0][3] += a2.x * b4.w;
                acc[1][0] += a2.y * b4.x; acc[1][1] += a2.y * b4.y;
                acc[1][2] += a2.y * b4.z; acc[1][3] += a2.y * b4.w;
            }
            if (t + 1 < 16) {
                storeAB(buf ^ 1);
                __syncthreads();
            }
        }

#pragma unroll
        for (int i = 0; i < 2; i++) {
            int row = m0 + ty * 2 + i;
            int col = n0 + tx * 4;
            uint32_t h0, l0, h1, l1;
            split2(acc[i][0], acc[i][1], h0, l0);
            split2(acc[i][2], acc[i][3], h1, l1);
            *(uint32_t*)(g_ihi + (size_t)row * 256 + col)     = h0;
            *(uint32_t*)(g_ihi + (size_t)row * 256 + col + 2) = h1;
            *(uint32_t*)(g_ilo + (size_t)row * 256 + col)     = l0;
            *(uint32_t*)(g_ilo + (size_t)row * 256 + col + 2) = l1;
        }
    }
}

// vectorized split-K reduction for v (float4 x16 partials per thread)
__global__ void reduce_v_kernel() {
    int q = blockIdx.x * blockDim.x + threadIdx.x;  // 0..16383
    if (q >= 16384) return;
    float4 s = *(const float4*)(g_partA + (size_t)q * 4);
#pragma unroll
    for (int p = 1; p < 16; p++) {
        float4 t = *(const float4*)(g_partA + (size_t)p * 65536 + (size_t)q * 4);
        s.x += t.x; s.y += t.y; s.z += t.z; s.w += t.w;
    }
    uint32_t h0, l0, h1, l1;
    split2(s.x, s.y, h0, l0);
    split2(s.z, s.w, h1, l1);
    *(uint32_t*)(g_vhi + (size_t)q * 4)     = h0;
    *(uint32_t*)(g_vhi + (size_t)q * 4 + 2) = h1;
    *(uint32_t*)(g_vlo + (size_t)q * 4)     = l0;
    *(uint32_t*)(g_vlo + (size_t)q * 4 + 2) = l1;
}

// ---------------------------------------------------------------------------
// HMMA box GEMM: C[128, 12544] = v @ W_box^T, K=512. 196 blocks 128x64.
// 2 CTAs/SM.
// ---------------------------------------------------------------------------
__global__ void __launch_bounds__(256, 2)
hmma_box(const float* __restrict__ Wbox)
{
    extern __shared__ __align__(1024) char smem[];
    uint32_t sbase = smem_u32(smem);
    int tid = threadIdx.x, w = tid >> 5, l = tid & 31;
    int n0 = blockIdx.x * 64;
    int kcta = n0 >> 8, o0 = n0 & 255;
    int wm = (w >> 1) * 32, wn = (w & 1) * 32;

    uint4 aR[8];
    float4 bRf[4];
    auto loadg = [&](int t) {
        int k0 = t * 64;
#pragma unroll
        for (int i = 0; i < 4; i++) {
            int s = tid + i * 256, r = s >> 3, c = s & 7;
            size_t eo = (size_t)r * 512 + k0 + c * 8;
            aR[i]     = *(const uint4*)(g_vhi + eo);
            aR[i + 4] = *(const uint4*)(g_vlo + eo);
        }
#pragma unroll
        for (int i = 0; i < 2; i++) {
            int s = tid + i * 256, r = s >> 3, c = s & 7;
            const float* src = Wbox + (size_t)(n0 + r) * 512 + k0 + c * 8;
            bRf[2 * i]     = *(const float4*)src;
            bRf[2 * i + 1] = *(const float4*)(src + 4);
        }
    };
    auto storeb = [&](int buf) {
        char* base = smem + buf * BOXB;
#pragma unroll
        for (int i = 0; i < 4; i++) {
            int s = tid + i * 256, r = s >> 3, c = s & 7;
            uint32_t off = SWZ128((uint32_t)(r * 128 + c * 16));
            *(uint4*)(base + off)         = aR[i];
            *(uint4*)(base + 16384 + off) = aR[i + 4];
        }
#pragma unroll
        for (int i = 0; i < 2; i++) {
            int s = tid + i * 256, r = s >> 3, c = s & 7;
            float fv[8] = {bRf[2*i].x, bRf[2*i].y, bRf[2*i].z, bRf[2*i].w,
                           bRf[2*i+1].x, bRf[2*i+1].y, bRf[2*i+1].z, bRf[2*i+1].w};
            uint4 h4, l4;
            split2(fv[0], fv[1], h4.x, l4.x); split2(fv[2], fv[3], h4.y, l4.y);
            split2(fv[4], fv[5], h4.z, l4.z); split2(fv[6], fv[7], h4.w, l4.w);
            uint32_t off = SWZ128((uint32_t)(r * 128 + c * 16));
            *(uint4*)(base + 32768 + off) = h4;
            *(uint4*)(base + 40960 + off) = l4;
        }
    };

    float acc[2][4][4];
#pragma unroll
    for (int s = 0; s < 2; s++)
#pragma unroll
        for (int j = 0; j < 4; j++)
#pragma unroll
            for (int q = 0; q < 4; q++) acc[s][j][q] = 0.f;

    loadg(0); storeb(0);
    __syncthreads();

    for (int t = 0; t < 8; t++) {
        int buf = t & 1;
        if (t + 1 < 8) loadg(t + 1);
        uint32_t B0 = sbase + buf * BOXB;
#pragma unroll
        for (int kk = 0; kk < 4; kk++) {
            uint32_t ah[2][4], al[2][4];
#pragma unroll
            for (int s = 0; s < 2; s++) {
                int row = wm + s * 16 + (l & 15);
                int ch = kk * 2 + (l >> 4);
                uint32_t off = SWZ128((uint32_t)(row * 128 + ch * 16));
                LDSM4(ah[s], B0 + off);
                LDSM4(al[s], B0 + 16384 + off);
            }
#pragma unroll
            for (int p = 0; p < 2; p++) {
                int nrow = wn + p * 16 + (l & 7) + ((l >> 4) << 3);
                int ch = kk * 2 + ((l >> 3) & 1);
                uint32_t off = SWZ128((uint32_t)(nrow * 128 + ch * 16));
                uint32_t bh[4], bl[4];
                LDSM4(bh, B0 + 32768 + off);
                LDSM4(bl, B0 + 40960 + off);
#pragma unroll
                for (int s = 0; s < 2; s++) {
                    mma_bf16(acc[s][2*p],     ah[s], bh);
                    mma_bf16(acc[s][2*p],     ah[s], bl);
                    mma_bf16(acc[s][2*p],     al[s], bh);
                    mma_bf16(acc[s][2*p + 1], ah[s], bh + 2);
                    mma_bf16(acc[s][2*p + 1], ah[s], bl + 2);
                    mma_bf16(acc[s][2*p + 1], al[s], bh + 2);
                }
            }
        }
        if (t + 1 < 8) {
            storeb(buf ^ 1);
            __syncthreads();
        }
    }

#pragma unroll
    for (int s = 0; s < 2; s++) {
        int m = wm + s * 16 + (l >> 2);
#pragma unroll
        for (int j = 0; j < 4; j++) {
            int o = o0 + wn + j * 8 + (l & 3) * 2;
            uint32_t hi, lo;
            split2(acc[s][j][0], acc[s][j][1], hi, lo);
            size_t b0 = (size_t)(m * 49 + kcta) * 256 + o;
            *(uint32_t*)(g_bhi + b0) = hi;
            *(uint32_t*)(g_blo + b0) = lo;
            split2(acc[s][j][2], acc[s][j][3], hi, lo);
            size_t b1 = (size_t)((m + 8) * 49 + kcta) * 256 + o;
            *(uint32_t*)(g_bhi + b1) = hi;
            *(uint32_t*)(g_blo + b1) = lo;
        }
    }
}

// ---------------------------------------------------------------------------
// HMMA Gxy GEMM + fused assemble + indices: 98 blocks 64x160, K=256.
// ---------------------------------------------------------------------------
#define GXYB 57344
__global__ void __launch_bounds__(256)
hmma_gxy(float* __restrict__ outg, const float* __restrict__ rois,
         void* d_out, int mode)
{
    extern __shared__ __align__(1024) char smem[];
    uint32_t sbase = smem_u32(smem);
    int tid = threadIdx.x, w = tid >> 5, l = tid & 31;
    int m0 = blockIdx.x * 64;
    int wm = (w >> 1) * 16, wn = (w & 1) * 80;

    if (mode && blockIdx.x == 0 && tid < N_ROIS) {
        long long v = (long long)rois[tid * 5];
        if (mode == 1) ((float*)d_out)[tid] = (float)v;
        else           ((long long*)d_out)[tid] = v;
    }

    uint4 aR[4], bR[10];
    auto loadg = [&](int t) {
        int k0 = t * 64;
#pragma unroll
        for (int i = 0; i < 2; i++) {
            int s = tid + i * 256, r = s >> 3, c = s & 7;
            size_t eo = (size_t)(m0 + r) * 256 + k0 + c * 8;
            aR[i]     = *(const uint4*)(g_bhi + eo);
            aR[i + 2] = *(const uint4*)(g_blo + eo);
        }
#pragma unroll
        for (int i = 0; i < 5; i++) {
            int s = tid + i * 256, r = s >> 3, c = s & 7;
            size_t eo = (size_t)r * 256 + k0 + c * 8;
            bR[i]     = *(const uint4*)(g_ihi + eo);
            bR[i + 5] = *(const uint4*)(g_ilo + eo);
        }
    };
    auto storeb = [&](int buf) {
        char* base = smem + buf * GXYB;
#pragma unroll
        for (int i = 0; i < 2; i++) {
            int s = tid + i * 256, r = s >> 3, c = s & 7;
            uint32_t off = SWZ128((uint32_t)(r * 128 + c * 16));
            *(uint4*)(base + off)        = aR[i];
            *(uint4*)(base + 8192 + off) = aR[i + 2];
        }
#pragma unroll
        for (int i = 0; i < 5; i++) {
            int s = tid + i * 256, r = s >> 3, c = s & 7;
            uint32_t off = SWZ128((uint32_t)(r * 128 + c * 16));
            *(uint4*)(base + 16384 + off) = bR[i];
            *(uint4*)(base + 36864 + off) = bR[i + 5];
        }
    };

    float acc[10][4];
#pragma unroll
    for (int j = 0; j < 10; j++)
#pragma unroll
        for (int q = 0; q < 4; q++) acc[j][q] = 0.f;

    loadg(0); storeb(0);
    __syncthreads();

    for (int t = 0; t < 4; t++) {
        int buf = t & 1;
        if (t + 1 < 4) loadg(t + 1);
        uint32_t B0 = sbase + buf * GXYB;
#pragma unroll
        for (int kk = 0; kk < 4; kk++) {
            uint32_t ah[4], al[4];
            {
                int row = wm + (l & 15);
                int ch = kk * 2 + (l >> 4);
                uint32_t off = SWZ128((uint32_t)(row * 128 + ch * 16));
                LDSM4(ah, B0 + off);
                LDSM4(al, B0 + 8192 + off);
            }
#pragma unroll
            for (int p = 0; p < 5; p++) {
                int nrow = wn + p * 16 + (l & 7) + ((l >> 4) << 3);
                int ch = kk * 2 + ((l >> 3) & 1);
                uint32_t off = SWZ128((uint32_t)(nrow * 128 + ch * 16));
                uint32_t bh[4], bl[4];
                LDSM4(bh, B0 + 16384 + off);
                LDSM4(bl, B0 + 36864 + off);
                mma_bf16(acc[2*p],     ah, bh);
                mma_bf16(acc[2*p],     ah, bl);
                mma_bf16(acc[2*p],     al, bh);
                mma_bf16(acc[2*p + 1], ah, bh + 2);
                mma_bf16(acc[2*p + 1], ah, bl + 2);
                mma_bf16(acc[2*p + 1], al, bh + 2);
            }
        }
        if (t + 1 < 4) {
            storeb(buf ^ 1);
            __syncthreads();
        }
    }

    // fused assemble
    __syncthreads();
    float* sxy = (float*)smem;
    {
        int row = wm + (l >> 2);
#pragma unroll
        for (int j = 0; j < 10; j++) {
            int col = wn + j * 8 + (l & 3) * 2;
            sxy[row * 160 + col]           = acc[j][0];
            sxy[row * 160 + col + 1]       = acc[j][1];
            sxy[(row + 8) * 160 + col]     = acc[j][2];
            sxy[(row + 8) * 160 + col + 1] = acc[j][3];
        }
    }
    __syncthreads();

    for (int idx = tid; idx < 64 * 1536; idx += 256) {
        int nkl = idx / 1536, rem = idx - nkl * 1536;
        int h = rem / 24, w4 = (rem - h * 24) * 4;
        const float* rowp = sxy + nkl * 160;
        float gx = rowp[h];
        float4 v = make_float4(gx + rowp[64 + w4 + 0], gx + rowp[64 + w4 + 1],
                               gx + rowp[64 + w4 + 2], gx + rowp[64 + w4 + 3]);
        *(float4*)(outg + (size_t)(m0 + nkl) * 6144 + h * 96 + w4) = v;
    }
}

// ---------------------------------------------------------------------------
extern "C" void kernel_launch(void* const* d_in, const int* in_sizes, int n_in,
                              void* d_out, int out_size)
{
    const float* rois  = (const float*)d_in[1];
    const float* V_box = (const float*)d_in[2];
    const float* W_box = (const float*)d_in[3];
    const float* W_im  = (const float*)d_in[4];

    cudaFuncSetAttribute(hmma_v_img, cudaFuncAttributeMaxDynamicSharedMemorySize, 2 * BOXB);
    cudaFuncSetAttribute(hmma_box,   cudaFuncAttributeMaxDynamicSharedMemorySize, 2 * BOXB);
    cudaFuncSetAttribute(hmma_gxy,   cudaFuncAttributeMaxDynamicSharedMemorySize, 2 * GXYB);

    long long extra = (long long)out_size - GEO_SIZE;
    int mode = (extra == 128) ? 1 : (extra == 256 ? 2 : 0);
    float* outg = (float*)d_out + (extra > 0 ? extra : 0);

    // 1) all embeddings (rois -> bf16 hi/lo, range -> fp32)
    emb_all_kernel<<<832, 256>>>(rois);

    // 2) fused: v split-K HMMA (128 blocks) + img SIMT GEMM (20 blocks)
    hmma_v_img<<<148, 256, 2 * BOXB>>>(V_box, W_im);

    // 3) reduce v partials -> bf16 hi/lo
    reduce_v_kernel<<<64, 256>>>();

    // 4) box = v @ W_box^T  (HMMA bf16x3, 2 CTAs/SM)
    hmma_box<<<196, 256, 2 * BOXB>>>(W_box);

    // 5) Gxy + fused assemble + indices
    hmma_gxy<<<98, 256, 2 * GXYB>>>(outg, rois, d_out, mode);
}

// round 11
// speedup vs baseline: 3.8299x; 1.0455x over previous
#include <cuda_runtime.h>
#include <cuda_bf16.h>
#include <cstdint>

// ---------------------------------------------------------------------------
// GeometricTerm: algebraic collapse + HMMA (mma.sync bf16x3) GEMM chain.
//   geo[nk,h,w] = Gx[nk,h] + Gy[nk,w]
// 5 launches: emb_all -> {hmma_v | img} -> reduce_v -> hmma_box -> gxy+assemble
// R11 = R10 resubmit: box rebalanced to 392 blocks of 128x32 + cp.async A-path.
// ---------------------------------------------------------------------------

#define N_ROIS 128
#define CEMB   512
#define HH     64
#define WW     96
#define KO     12544
#define NK     6272
#define GEO_SIZE 38535168ll

__device__ __nv_bfloat16 g_ehi[N_ROIS * 2048], g_elo[N_ROIS * 2048];
__device__ float g_ex   [HH * CEMB];
__device__ float g_ey   [WW * CEMB];
__device__ float g_partA[16 * N_ROIS * CEMB];
__device__ __nv_bfloat16 g_vhi[N_ROIS * CEMB], g_vlo[N_ROIS * CEMB];
__device__ __nv_bfloat16 g_ihi[160 * 256],     g_ilo[160 * 256];
__device__ __nv_bfloat16 g_bhi[NK * 256],      g_blo[NK * 256];

// ---------------------------------------------------------------------------
// helpers
// ---------------------------------------------------------------------------
__device__ __forceinline__ uint32_t smem_u32(const void* p) {
    uint32_t a;
    asm("{ .reg .u64 t; cvta.to.shared.u64 t, %1; cvt.u32.u64 %0, t; }"
        : "=r"(a) : "l"(p));
    return a;
}
#define SWZ128(x) ((x) ^ (((x) >> 3) & 0x70))

#define LDSM4(r, a) \
    asm volatile("ldmatrix.sync.aligned.m8n8.x4.shared.b16 {%0,%1,%2,%3}, [%4];" \
        : "=r"((r)[0]), "=r"((r)[1]), "=r"((r)[2]), "=r"((r)[3]) : "r"(a))

#define CP_ASYNC16(dst, src) \
    asm volatile("cp.async.cg.shared.global [%0], [%1], 16;" :: "r"(dst), "l"(src))
#define CP_COMMIT() asm volatile("cp.async.commit_group;")
#define CP_WAIT0()  asm volatile("cp.async.wait_group 0;" ::: "memory")

__device__ __forceinline__ void mma_bf16(float* d, const uint32_t* a, const uint32_t* b) {
    asm volatile("mma.sync.aligned.m16n8k16.row.col.f32.bf16.bf16.f32 "
        "{%0,%1,%2,%3}, {%4,%5,%6,%7}, {%8,%9}, {%0,%1,%2,%3};"
        : "+f"(d[0]), "+f"(d[1]), "+f"(d[2]), "+f"(d[3])
        : "r"(a[0]), "r"(a[1]), "r"(a[2]), "r"(a[3]), "r"(b[0]), "r"(b[1]));
}

__device__ __forceinline__ void split2(float a, float b, uint32_t& hi, uint32_t& lo) {
    __nv_bfloat16 ha = __float2bfloat16(a), hb = __float2bfloat16(b);
    __nv_bfloat16 la = __float2bfloat16(a - __bfloat162float(ha));
    __nv_bfloat16 lb = __float2bfloat16(b - __bfloat162float(hb));
    hi = (uint32_t)__bfloat16_as_ushort(ha) | ((uint32_t)__bfloat16_as_ushort(hb) << 16);
    lo = (uint32_t)__bfloat16_as_ushort(la) | ((uint32_t)__bfloat16_as_ushort(lb) << 16);
}

// ---------------------------------------------------------------------------
// embeddings (fp32 exp2f + sinf/cosf)
// ---------------------------------------------------------------------------
__device__ __forceinline__ float emb_f(float z, int i) {
    const float NEG_L2_1000_OVER_C = -9.965784284662087f / 512.0f;
    float e = (i < 256) ? (float)(2 * i + 1) : (float)(2 * (i - 256));
    float a = z * exp2f(e * NEG_L2_1000_OVER_C);
    return (i < 256) ? sinf(a) : cosf(a);
}

__global__ void emb_all_kernel(const float* __restrict__ rois) {
    int bid = blockIdx.x, tid = threadIdx.x;
    if (bid < 512) {
        int p = bid * 256 + tid;
        int idx = p * 2;
        int n = idx >> 11, d = idx & 2047;
        int j = d >> 9, i = d & 511;
        float z = rois[n * 5 + 1 + j];
        float v0 = emb_f(z, i), v1 = emb_f(z, i + 1);
        uint32_t hi, lo;
        split2(v0, v1, hi, lo);
        *(uint32_t*)(g_ehi + idx) = hi;
        *(uint32_t*)(g_elo + idx) = lo;
    } else {
        int idx = (bid - 512) * 256 + tid;
        int r = idx >> 9, i = idx & 511;
        float z = (float)(r < HH ? r : r - HH);
        float val = emb_f(z, i);
        if (r < HH) g_ex[r * CEMB + i] = val;
        else        g_ey[(r - HH) * CEMB + i] = val;
    }
}

// ---------------------------------------------------------------------------
// Fused: blocks 0..127 = hmma_v (split-K x16); blocks 128..147 = img SIMT GEMM
// ---------------------------------------------------------------------------
#define BOXB 49152
__global__ void __launch_bounds__(256)
hmma_v_img(const float* __restrict__ Vbox, const float* __restrict__ Wim)
{
    extern __shared__ __align__(1024) char smem[];
    int tid = threadIdx.x;

    if (blockIdx.x < 128) {
        uint32_t sbase = smem_u32(smem);
        int w = tid >> 5, l = tid & 31;
        int n0 = (blockIdx.x & 7) * 64;
        int kstart = (blockIdx.x >> 3) * 128;
        int wm = (w >> 1) * 32, wn = (w & 1) * 32;

        uint4 aR[8];
        float4 bRf[4];
        auto loadg = [&](int t) {
            int k0 = kstart + t * 64;
#pragma unroll
            for (int i = 0; i < 4; i++) {
                int s = tid + i * 256, r = s >> 3, c = s & 7;
                size_t eo = (size_t)r * 2048 + k0 + c * 8;
                aR[i]     = *(const uint4*)(g_ehi + eo);
                aR[i + 4] = *(const uint4*)(g_elo + eo);
            }
#pragma unroll
            for (int i = 0; i < 2; i++) {
                int s = tid + i * 256, r = s >> 3, c = s & 7;
                const float* src = Vbox + (size_t)(n0 + r) * 2048 + k0 + c * 8;
                bRf[2 * i]     = *(const float4*)src;
                bRf[2 * i + 1] = *(const float4*)(src + 4);
            }
        };
        auto storeb = [&](int buf) {
            char* base = smem + buf * BOXB;
#pragma unroll
            for (int i = 0; i < 4; i++) {
                int s = tid + i * 256, r = s >> 3, c = s & 7;
                uint32_t off = SWZ128((uint32_t)(r * 128 + c * 16));
                *(uint4*)(base + off)         = aR[i];
                *(uint4*)(base + 16384 + off) = aR[i + 4];
            }
#pragma unroll
            for (int i = 0; i < 2; i++) {
                int s = tid + i * 256, r = s >> 3, c = s & 7;
                float fv[8] = {bRf[2*i].x, bRf[2*i].y, bRf[2*i].z, bRf[2*i].w,
                               bRf[2*i+1].x, bRf[2*i+1].y, bRf[2*i+1].z, bRf[2*i+1].w};
                uint4 h4, l4;
                split2(fv[0], fv[1], h4.x, l4.x); split2(fv[2], fv[3], h4.y, l4.y);
                split2(fv[4], fv[5], h4.z, l4.z); split2(fv[6], fv[7], h4.w, l4.w);
                uint32_t off = SWZ128((uint32_t)(r * 128 + c * 16));
                *(uint4*)(base + 32768 + off) = h4;
                *(uint4*)(base + 40960 + off) = l4;
            }
        };

        float acc[2][4][4];
#pragma unroll
        for (int s = 0; s < 2; s++)
#pragma unroll
            for (int j = 0; j < 4; j++)
#pragma unroll
                for (int q = 0; q < 4; q++) acc[s][j][q] = 0.f;

        loadg(0); storeb(0);
        __syncthreads();

        for (int t = 0; t < 2; t++) {
            int buf = t & 1;
            if (t + 1 < 2) loadg(t + 1);
            uint32_t B0 = sbase + buf * BOXB;
#pragma unroll
            for (int kk = 0; kk < 4; kk++) {
                uint32_t ah[2][4], al[2][4];
#pragma unroll
                for (int s = 0; s < 2; s++) {
                    int row = wm + s * 16 + (l & 15);
                    int ch = kk * 2 + (l >> 4);
                    uint32_t off = SWZ128((uint32_t)(row * 128 + ch * 16));
                    LDSM4(ah[s], B0 + off);
                    LDSM4(al[s], B0 + 16384 + off);
                }
#pragma unroll
                for (int p = 0; p < 2; p++) {
                    int nrow = wn + p * 16 + (l & 7) + ((l >> 4) << 3);
                    int ch = kk * 2 + ((l >> 3) & 1);
                    uint32_t off = SWZ128((uint32_t)(nrow * 128 + ch * 16));
                    uint32_t bh[4], bl[4];
                    LDSM4(bh, B0 + 32768 + off);
                    LDSM4(bl, B0 + 40960 + off);
#pragma unroll
                    for (int s = 0; s < 2; s++) {
                        mma_bf16(acc[s][2*p],     ah[s], bh);
                        mma_bf16(acc[s][2*p],     ah[s], bl);
                        mma_bf16(acc[s][2*p],     al[s], bh);
                        mma_bf16(acc[s][2*p + 1], ah[s], bh + 2);
                        mma_bf16(acc[s][2*p + 1], ah[s], bl + 2);
                        mma_bf16(acc[s][2*p + 1], al[s], bh + 2);
                    }
                }
            }
            if (t + 1 < 2) {
                storeb(buf ^ 1);
                __syncthreads();
            }
        }

        float* Cp = g_partA + (size_t)(blockIdx.x >> 3) * (N_ROIS * CEMB);
#pragma unroll
        for (int s = 0; s < 2; s++) {
            int m = wm + s * 16 + (l >> 2);
#pragma unroll
            for (int j = 0; j < 4; j++) {
                int o = n0 + wn + j * 8 + (l & 3) * 2;
                *(float2*)(Cp + (size_t)m * 512 + o) = make_float2(acc[s][j][0], acc[s][j][1]);
                *(float2*)(Cp + (size_t)(m + 8) * 512 + o) = make_float2(acc[s][j][2], acc[s][j][3]);
            }
        }
    } else {
        // img: [160,256] = [ex;ey] @ W_im halves^T  (SIMT 32x64, K=512)
        float* As = (float*)smem;
        float* Bs = (float*)(smem + 8192);
        int b = blockIdx.x - 128;
        int m0 = (b % 5) * 32;
        int n0 = (b / 5) * 64;
        const float* Abase = (m0 < HH) ? g_ex + (size_t)m0 * CEMB
                                       : g_ey + (size_t)(m0 - HH) * CEMB;
        int boff = (m0 < HH) ? 0 : 512;
        int tx = tid & 15, ty = tid >> 4;

        float4 aR;
        float4 bR[2];
        auto loadA = [&](int t) {
            int r = tid >> 3, kq = (tid & 7) * 4;
            aR = *(const float4*)(Abase + (size_t)r * CEMB + t * 32 + kq);
        };
        auto loadB = [&](int t) {
#pragma unroll
            for (int i = 0; i < 2; i++) {
                int f = tid + i * 256, r = f >> 3, kq = (f & 7) * 4;
                bR[i] = *(const float4*)(Wim + (size_t)(n0 + r) * 1024 + boff + t * 32 + kq);
            }
        };
        auto storeAB = [&](int buf) {
            int r = tid >> 3, kq = (tid & 7) * 4;
            As[buf * 1024 + (kq + 0) * 32 + r] = aR.x;
            As[buf * 1024 + (kq + 1) * 32 + r] = aR.y;
            As[buf * 1024 + (kq + 2) * 32 + r] = aR.z;
            As[buf * 1024 + (kq + 3) * 32 + r] = aR.w;
#pragma unroll
            for (int i = 0; i < 2; i++) {
                int f = tid + i * 256, rr = f >> 3, kq2 = (f & 7) * 4;
                Bs[buf * 2048 + (kq2 + 0) * 64 + rr] = bR[i].x;
                Bs[buf * 2048 + (kq2 + 1) * 64 + rr] = bR[i].y;
                Bs[buf * 2048 + (kq2 + 2) * 64 + rr] = bR[i].z;
                Bs[buf * 2048 + (kq2 + 3) * 64 + rr] = bR[i].w;
            }
        };

        float acc[2][4];
#pragma unroll
        for (int i = 0; i < 2; i++)
#pragma unroll
            for (int j = 0; j < 4; j++) acc[i][j] = 0.f;

        loadA(0); loadB(0); storeAB(0);
        __syncthreads();

        for (int t = 0; t < 16; t++) {
            int buf = t & 1;
            if (t + 1 < 16) { loadA(t + 1); loadB(t + 1); }
#pragma unroll
            for (int kk = 0; kk < 32; kk++) {
                float2 a2 = *(const float2*)&As[buf * 1024 + kk * 32 + ty * 2];
                float4 b4 = *(const float4*)&Bs[buf * 2048 + kk * 64 + tx * 4];
                acc[0][0] += a2.x * b4.x; acc[0][1] += a2.x * b4.y;
                acc[0][2] += a2.x * b4.z; acc[0][3] += a2.x * b4.w;
                acc[1][0] += a2.y * b4.x; acc[1][1] += a2.y * b4.y;
                acc[1][2] += a2.y * b4.z; acc[1][3] += a2.y * b4.w;
            }
            if (t + 1 < 16) {
                storeAB(buf ^ 1);
                __syncthreads();
            }
        }

#pragma unroll
        for (int i = 0; i < 2; i++) {
            int row = m0 + ty * 2 + i;
            int col = n0 + tx * 4;
            uint32_t h0, l0, h1, l1;
            split2(acc[i][0], acc[i][1], h0, l0);
            split2(acc[i][2], acc[i][3], h1, l1);
            *(uint32_t*)(g_ihi + (size_t)row * 256 + col)     = h0;
            *(uint32_t*)(g_ihi + (size_t)row * 256 + col + 2) = h1;
            *(uint32_t*)(g_ilo + (size_t)row * 256 + col)     = l0;
            *(uint32_t*)(g_ilo + (size_t)row * 256 + col + 2) = l1;
        }
    }
}

// vectorized split-K reduction for v
__global__ void reduce_v_kernel() {
    int q = blockIdx.x * blockDim.x + threadIdx.x;
    if (q >= 16384) return;
    float4 s = *(const float4*)(g_partA + (size_t)q * 4);
#pragma unroll
    for (int p = 1; p < 16; p++) {
        float4 t = *(const float4*)(g_partA + (size_t)p * 65536 + (size_t)q * 4);
        s.x += t.x; s.y += t.y; s.z += t.z; s.w += t.w;
    }
    uint32_t h0, l0, h1, l1;
    split2(s.x, s.y, h0, l0);
    split2(s.z, s.w, h1, l1);
    *(uint32_t*)(g_vhi + (size_t)q * 4)     = h0;
    *(uint32_t*)(g_vhi + (size_t)q * 4 + 2) = h1;
    *(uint32_t*)(g_vlo + (size_t)q * 4)     = l0;
    *(uint32_t*)(g_vlo + (size_t)q * 4 + 2) = l1;
}

// ---------------------------------------------------------------------------
// HMMA box GEMM: C[128, 12544] = v @ W_box^T, K=512.
// 392 blocks of 128M x 32N (balance: ~1.5x T_tile vs 2.0x at 196 blocks).
// A (bf16 hi/lo) via cp.async; B (fp32) via regs + split.
// buf (40960B): Ahi 16K | Alo 16K | Bhi 4K | Blo 4K.  2 bufs = 80K -> 2 CTA/SM.
// ---------------------------------------------------------------------------
#define BOXB2 40960
__global__ void __launch_bounds__(256, 2)
hmma_box(const float* __restrict__ Wbox)
{
    extern __shared__ __align__(1024) char smem[];
    uint32_t sbase = smem_u32(smem);
    int tid = threadIdx.x, w = tid >> 5, l = tid & 31;
    int n0 = blockIdx.x * 32;
    int kcta = n0 >> 8, o0 = n0 & 255;
    int wm = (w >> 1) * 32, wn = (w & 1) * 16;

    auto issueA = [&](int t, int buf) {
        uint32_t base = sbase + buf * BOXB2;
        int k0 = t * 64;
#pragma unroll
        for (int i = 0; i < 4; i++) {
            int s = tid + i * 256, r = s >> 3, c = s & 7;
            size_t eo = (size_t)r * 512 + k0 + c * 8;
            uint32_t off = SWZ128((uint32_t)(r * 128 + c * 16));
            CP_ASYNC16(base + off,         g_vhi + eo);
            CP_ASYNC16(base + 16384 + off, g_vlo + eo);
        }
        CP_COMMIT();
    };

    float4 bRf[2];
    auto loadB = [&](int t) {
        int r = tid >> 3, c = tid & 7;
        const float* src = Wbox + (size_t)(n0 + r) * 512 + t * 64 + c * 8;
        bRf[0] = *(const float4*)src;
        bRf[1] = *(const float4*)(src + 4);
    };
    auto storeB = [&](int buf) {
        char* base = smem + buf * BOXB2;
        int r = tid >> 3, c = tid & 7;
        float fv[8] = {bRf[0].x, bRf[0].y, bRf[0].z, bRf[0].w,
                       bRf[1].x, bRf[1].y, bRf[1].z, bRf[1].w};
        uint4 h4, l4;
        split2(fv[0], fv[1], h4.x, l4.x); split2(fv[2], fv[3], h4.y, l4.y);
        split2(fv[4], fv[5], h4.z, l4.z); split2(fv[6], fv[7], h4.w, l4.w);
        uint32_t off = SWZ128((uint32_t)(r * 128 + c * 16));
        *(uint4*)(base + 32768 + off) = h4;
        *(uint4*)(base + 36864 + off) = l4;
    };

    float acc[2][2][4];
#pragma unroll
    for (int s = 0; s < 2; s++)
#pragma unroll
        for (int j = 0; j < 2; j++)
#pragma unroll
            for (int q = 0; q < 4; q++) acc[s][j][q] = 0.f;

    issueA(0, 0);
    loadB(0); storeB(0);
    CP_WAIT0();
    __syncthreads();

    for (int t = 0; t < 8; t++) {
        int buf = t & 1;
        if (t + 1 < 8) { issueA(t + 1, buf ^ 1); loadB(t + 1); }

        uint32_t B0 = sbase + buf * BOXB2;
#pragma unroll
        for (int kk = 0; kk < 4; kk++) {
            uint32_t ah[2][4], al[2][4];
#pragma unroll
            for (int s = 0; s < 2; s++) {
                int row = wm + s * 16 + (l & 15);
                int ch = kk * 2 + (l >> 4);
                uint32_t off = SWZ128((uint32_t)(row * 128 + ch * 16));
                LDSM4(ah[s], B0 + off);
                LDSM4(al[s], B0 + 16384 + off);
            }
            int nrow = wn + (l & 7) + ((l >> 4) << 3);
            int ch = kk * 2 + ((l >> 3) & 1);
            uint32_t off = SWZ128((uint32_t)(nrow * 128 + ch * 16));
            uint32_t bh[4], bl[4];
            LDSM4(bh, B0 + 32768 + off);
            LDSM4(bl, B0 + 36864 + off);
#pragma unroll
            for (int s = 0; s < 2; s++) {
                mma_bf16(acc[s][0], ah[s], bh);
                mma_bf16(acc[s][0], ah[s], bl);
                mma_bf16(acc[s][0], al[s], bh);
                mma_bf16(acc[s][1], ah[s], bh + 2);
                mma_bf16(acc[s][1], ah[s], bl + 2);
                mma_bf16(acc[s][1], al[s], bh + 2);
            }
        }
        if (t + 1 < 8) {
            storeB(buf ^ 1);
            CP_WAIT0();
            __syncthreads();
        }
    }

#pragma unroll
    for (int s = 0; s < 2; s++) {
        int m = wm + s * 16 + (l >> 2);
#pragma unroll
        for (int j = 0; j < 2; j++) {
            int o = o0 + wn + j * 8 + (l & 3) * 2;
            uint32_t hi, lo;
            split2(acc[s][j][0], acc[s][j][1], hi, lo);
            size_t b0 = (size_t)(m * 49 + kcta) * 256 + o;
            *(uint32_t*)(g_bhi + b0) = hi;
            *(uint32_t*)(g_blo + b0) = lo;
            split2(acc[s][j][2], acc[s][j][3], hi, lo);
            size_t b1 = (size_t)((m + 8) * 49 + kcta) * 256 + o;
            *(uint32_t*)(g_bhi + b1) = hi;
            *(uint32_t*)(g_blo + b1) = lo;
        }
    }
}

// ---------------------------------------------------------------------------
// HMMA Gxy GEMM + fused assemble + indices: 98 blocks 64x160, K=256.
// ---------------------------------------------------------------------------
#define GXYB 57344
__global__ void __launch_bounds__(256)
hmma_gxy(float* __restrict__ outg, const float* __restrict__ rois,
         void* d_out, int mode)
{
    extern __shared__ __align__(1024) char smem[];
    uint32_t sbase = smem_u32(smem);
    int tid = threadIdx.x, w = tid >> 5, l = tid & 31;
    int m0 = blockIdx.x * 64;
    int wm = (w >> 1) * 16, wn = (w & 1) * 80;

    if (mode && blockIdx.x == 0 && tid < N_ROIS) {
        long long v = (long long)rois[tid * 5];
        if (mode == 1) ((float*)d_out)[tid] = (float)v;
        else           ((long long*)d_out)[tid] = v;
    }

    uint4 aR[4], bR[10];
    auto loadg = [&](int t) {
        int k0 = t * 64;
#pragma unroll
        for (int i = 0; i < 2; i++) {
            int s = tid + i * 256, r = s >> 3, c = s & 7;
            size_t eo = (size_t)(m0 + r) * 256 + k0 + c * 8;
            aR[i]     = *(const uint4*)(g_bhi + eo);
            aR[i + 2] = *(const uint4*)(g_blo + eo);
        }
#pragma unroll
        for (int i = 0; i < 5; i++) {
            int s = tid + i * 256, r = s >> 3, c = s & 7;
            size_t eo = (size_t)r * 256 + k0 + c * 8;
            bR[i]     = *(const uint4*)(g_ihi + eo);
            bR[i + 5] = *(const uint4*)(g_ilo + eo);
        }
    };
    auto storeb = [&](int buf) {
        char* base = smem + buf * GXYB;
#pragma unroll
        for (int i = 0; i < 2; i++) {
            int s = tid + i * 256, r = s >> 3, c = s & 7;
            uint32_t off = SWZ128((uint32_t)(r * 128 + c * 16));
            *(uint4*)(base + off)        = aR[i];
            *(uint4*)(base + 8192 + off) = aR[i + 2];
        }
#pragma unroll
        for (int i = 0; i < 5; i++) {
            int s = tid + i * 256, r = s >> 3, c = s & 7;
            uint32_t off = SWZ128((uint32_t)(r * 128 + c * 16));
            *(uint4*)(base + 16384 + off) = bR[i];
            *(uint4*)(base + 36864 + off) = bR[i + 5];
        }
    };

    float acc[10][4];
#pragma unroll
    for (int j = 0; j < 10; j++)
#pragma unroll
        for (int q = 0; q < 4; q++) acc[j][q] = 0.f;

    loadg(0); storeb(0);
    __syncthreads();

    for (int t = 0; t < 4; t++) {
        int buf = t & 1;
        if (t + 1 < 4) loadg(t + 1);
        uint32_t B0 = sbase + buf * GXYB;
#pragma unroll
        for (int kk = 0; kk < 4; kk++) {
            uint32_t ah[4], al[4];
            {
                int row = wm + (l & 15);
                int ch = kk * 2 + (l >> 4);
                uint32_t off = SWZ128((uint32_t)(row * 128 + ch * 16));
                LDSM4(ah, B0 + off);
                LDSM4(al, B0 + 8192 + off);
            }
#pragma unroll
            for (int p = 0; p < 5; p++) {
                int nrow = wn + p * 16 + (l & 7) + ((l >> 4) << 3);
                int ch = kk * 2 + ((l >> 3) & 1);
                uint32_t off = SWZ128((uint32_t)(nrow * 128 + ch * 16));
                uint32_t bh[4], bl[4];
                LDSM4(bh, B0 + 16384 + off);
                LDSM4(bl, B0 + 36864 + off);
                mma_bf16(acc[2*p],     ah, bh);
                mma_bf16(acc[2*p],     ah, bl);
                mma_bf16(acc[2*p],     al, bh);
                mma_bf16(acc[2*p + 1], ah, bh + 2);
                mma_bf16(acc[2*p + 1], ah, bl + 2);
                mma_bf16(acc[2*p + 1], al, bh + 2);
            }
        }
        if (t + 1 < 4) {
            storeb(buf ^ 1);
            __syncthreads();
        }
    }

    // fused assemble
    __syncthreads();
    float* sxy = (float*)smem;
    {
        int row = wm + (l >> 2);
#pragma unroll
        for (int j = 0; j < 10; j++) {
            int col = wn + j * 8 + (l & 3) * 2;
            sxy[row * 160 + col]           = acc[j][0];
            sxy[row * 160 + col + 1]       = acc[j][1];
            sxy[(row + 8) * 160 + col]     = acc[j][2];
            sxy[(row + 8) * 160 + col + 1] = acc[j][3];
        }
    }
    __syncthreads();

    for (int idx = tid; idx < 64 * 1536; idx += 256) {
        int nkl = idx / 1536, rem = idx - nkl * 1536;
        int h = rem / 24, w4 = (rem - h * 24) * 4;
        const float* rowp = sxy + nkl * 160;
        float gx = rowp[h];
        float4 v = make_float4(gx + rowp[64 + w4 + 0], gx + rowp[64 + w4 + 1],
                               gx + rowp[64 + w4 + 2], gx + rowp[64 + w4 + 3]);
        *(float4*)(outg + (size_t)(m0 + nkl) * 6144 + h * 96 + w4) = v;
    }
}

// ---------------------------------------------------------------------------
extern "C" void kernel_launch(void* const* d_in, const int* in_sizes, int n_in,
                              void* d_out, int out_size)
{
    const float* rois  = (const float*)d_in[1];
    const float* V_box = (const float*)d_in[2];
    const float* W_box = (const float*)d_in[3];
    const float* W_im  = (const float*)d_in[4];

    cudaFuncSetAttribute(hmma_v_img, cudaFuncAttributeMaxDynamicSharedMemorySize, 2 * BOXB);
    cudaFuncSetAttribute(hmma_box,   cudaFuncAttributeMaxDynamicSharedMemorySize, 2 * BOXB2);
    cudaFuncSetAttribute(hmma_gxy,   cudaFuncAttributeMaxDynamicSharedMemorySize, 2 * GXYB);

    long long extra = (long long)out_size - GEO_SIZE;
    int mode = (extra == 128) ? 1 : (extra == 256 ? 2 : 0);
    float* outg = (float*)d_out + (extra > 0 ? extra : 0);

    // 1) all embeddings
    emb_all_kernel<<<832, 256>>>(rois);

    // 2) fused: v split-K HMMA (128 blocks) + img SIMT GEMM (20 blocks)
    hmma_v_img<<<148, 256, 2 * BOXB>>>(V_box, W_im);

    // 3) reduce v partials -> bf16 hi/lo
    reduce_v_kernel<<<64, 256>>>();

    // 4) box = v @ W_box^T  (HMMA bf16x3, 392 balanced blocks, 2 CTAs/SM)
    hmma_box<<<392, 256, 2 * BOXB2>>>(W_box);

    // 5) Gxy + fused assemble + indices
    hmma_gxy<<<98, 256, 2 * GXYB>>>(outg, rois, d_out, mode);
}